// round 6
// baseline (speedup 1.0000x reference)
#include <cuda_runtime.h>
#include <cuda_bf16.h>
#include <math.h>
#include <stdint.h>

// ---------------------------------------------------------------------------
// EdgeFeatureConvBlock  (B=32, N=1024, P=8192, K=16, C_IN=32, E_IN=4, OUT=64)
// R6: mma.sync bf16 hi/lo split without duplicated hi-segment (w_lo fragments
//     re-read the x_hi groups). A-fragments pre-packed in smem (LDS.128).
//     S buffers [M][64] row-major; smem-transposed epilogue. 3 CTAs/SM.
// ---------------------------------------------------------------------------

#define BB   32
#define NN   1024
#define PP   8192
#define KK   16
#define CIN  32
#define EIN  4
#define O0   64
#define M_ALL (BB*NN*KK) // 524288
#define M_SC  (BB*NN)    // 32768
#define BN_EPS 1e-5f

// ------------------------- scratch (device globals) ------------------------
__device__ float g_S0[(size_t)O0 * M_ALL];   // [M][64]
__device__ float g_S1[(size_t)O0 * M_ALL];   // [M][64]
__device__ float g_scb[(size_t)O0 * M_SC];   // [M_SC][64]
__device__ int   g_topidx[M_ALL];
__device__ float g_eft[BB * EIN * NN * KK];
__device__ float g_sum[4][O0];
__device__ float g_sqsum[4][O0];
__device__ float g_a[4][O0];
__device__ float g_c[4][O0];
__device__ int   g_fb_list[BB * NN];
__device__ int   g_fb_count;

// ------------------------------ helpers -------------------------------------
__device__ __forceinline__ void split2(float x, __nv_bfloat16& h, __nv_bfloat16& l) {
    h = __float2bfloat16_rn(x);
    l = __float2bfloat16_rn(x - __bfloat162float(h));
}
__device__ __forceinline__ uint16_t bfbits(__nv_bfloat16 v) {
    return *(uint16_t*)&v;
}
// u16-index inside a 32B k-group for element j (0..15):
// order [0,1,8,9, 2,3,10,11, 4,5,12,13, 6,7,14,15]
__device__ __forceinline__ int pidx(int j) {
    return ((j & 6) << 1) | ((j & 8) >> 2) | (j & 1);
}
__device__ __forceinline__ void st32(char* p, const __nv_bfloat16* v) {
    *(uint4*)p        = ((const uint4*)v)[0];
    *(uint4*)(p + 16) = ((const uint4*)v)[1];
}
__device__ __forceinline__ void mma16816(float& d0, float& d1, float& d2, float& d3,
                                         uint32_t a0, uint32_t a1, uint32_t a2, uint32_t a3,
                                         uint32_t b0, uint32_t b1) {
    asm volatile(
        "mma.sync.aligned.m16n8k16.row.col.f32.bf16.bf16.f32 "
        "{%0,%1,%2,%3}, {%4,%5,%6,%7}, {%8,%9}, {%0,%1,%2,%3};"
        : "+f"(d0), "+f"(d1), "+f"(d2), "+f"(d3)
        : "r"(a0), "r"(a1), "r"(a2), "r"(a3), "r"(b0), "r"(b1));
}

// ------------------------------- init ---------------------------------------
__global__ void k_init() {
    int i = blockIdx.x * blockDim.x + threadIdx.x;
    int stride = gridDim.x * blockDim.x;
    for (int j = i; j < M_ALL; j += stride) g_topidx[j] = NN - 1;
    for (int j = i; j < BB * EIN * NN * KK; j += stride) g_eft[j] = 0.f;
    if (i < O0) {
        #pragma unroll
        for (int l = 0; l < 4; l++) { g_sum[l][i] = 0.f; g_sqsum[l][i] = 0.f; }
    }
    if (i == 0) g_fb_count = 0;
}

// ------------------------------ edge scatter --------------------------------
__global__ void k_scatter(const int* __restrict__ edge_list,
                          const float* __restrict__ edge_feat) {
    int t = blockIdx.x * blockDim.x + threadIdx.x;
    if (t >= BB * PP) return;
    int b = t / PP, p = t % PP;
    const int* src = edge_list + (size_t)b * 2 * PP;
    const int* dst = src + PP;
    int s = src[p];
    int lo = 0, hi = p;
    while (lo < hi) { int mid = (lo + hi) >> 1; if (src[mid] < s) lo = mid + 1; else hi = mid; }
    int rank = p - lo;
    if (rank < KK) {
        g_topidx[(b * NN + s) * KK + rank] = dst[p];
        #pragma unroll
        for (int e = 0; e < EIN; e++)
            g_eft[((b * EIN + e) * NN + s) * KK + rank] =
                edge_feat[((size_t)b * EIN + e) * PP + p];
    }
}

// --------------------------- fallback detection -----------------------------
__global__ void k_fb() {
    int t = blockIdx.x * blockDim.x + threadIdx.x;
    if (t >= BB * NN) return;
    if (g_topidx[t * KK] == NN - 1) {
        int pos = atomicAdd(&g_fb_count, 1);
        g_fb_list[pos] = t;
    }
}

// ------------------------------- knn (fallback rows only) -------------------
__global__ void k_knn(const float* __restrict__ points) {
    __shared__ float pd[NN];
    __shared__ float swv[4];
    __shared__ int   swi[4];
    int nfb = g_fb_count;
    for (int e = blockIdx.x; e < nfb; e += gridDim.x) {
        int bn = g_fb_list[e];
        int b = bn / NN, n = bn % NN;
        const float* px = points + (size_t)b * 2 * NN;
        const float* py = px + NN;
        float pxn = px[n], pyn = py[n];
        float xxn = pxn * pxn + pyn * pyn;
        for (int m = threadIdx.x; m < NN; m += blockDim.x) {
            float xm = px[m], ym = py[m];
            float inner = -2.0f * (pxn * xm + pyn * ym);
            float xxm = xm * xm + ym * ym;
            float v = -xxn - inner - xxm;
            pd[m] = (m == n) ? -INFINITY : v;
        }
        __syncthreads();
        for (int kk = 0; kk < KK; kk++) {
            float bv = -INFINITY; int bi = NN;
            for (int m = threadIdx.x; m < NN; m += blockDim.x) {
                float v = pd[m];
                if (v > bv) { bv = v; bi = m; }
            }
            #pragma unroll
            for (int off = 16; off; off >>= 1) {
                float ov = __shfl_down_sync(0xffffffffu, bv, off);
                int   oi = __shfl_down_sync(0xffffffffu, bi, off);
                if (ov > bv || (ov == bv && oi < bi)) { bv = ov; bi = oi; }
            }
            if ((threadIdx.x & 31) == 0) { swv[threadIdx.x >> 5] = bv; swi[threadIdx.x >> 5] = bi; }
            __syncthreads();
            if (threadIdx.x == 0) {
                float fv = swv[0]; int fi = swi[0];
                #pragma unroll
                for (int w = 1; w < 4; w++)
                    if (swv[w] > fv || (swv[w] == fv && swi[w] < fi)) { fv = swv[w]; fi = swi[w]; }
                g_topidx[bn * KK + kk] = fi;
                pd[fi] = -INFINITY;
            }
            __syncthreads();
        }
        __syncthreads();
    }
}

// --------------------------- mma GEMM + BN stats -----------------------------
// Sout[M][64] = (W[64][C] * X[C][M])^T.  X smem = [x_hi | x_lo] (NG=2*S16
// 16-wide k-groups); per k-group s three mma: whi*xhi + whi*xlo + wlo*xhi.
// CTA = 128 columns, 256 threads = 8 warps (4 channel-groups x 2 m-halves).
// MODE: 0 = gather-build 68ch, 1 = relu(bn(Sin)) [M][64], 2 = features.
template<int C, int MODE>
__global__ __launch_bounds__(256, 3) void k_gemm(
    const float* __restrict__ W,
    const float* __restrict__ F,
    float* __restrict__ Sout,
    int statsIdx, int prevIdx)
{
    constexpr int SEG  = (C + 15) & ~15;    // 80 / 64 / 32
    constexpr int S16  = SEG / 16;          // 5 / 4 / 2
    constexpr int NG   = 2 * S16;           // X k-groups (hi|lo)
    constexpr int RB0  = NG * 32;
    constexpr int ROWB = RB0 + (((RB0 % 128) == 32 || (RB0 % 128) == 96) ? 0 : 32);
    constexpr int WOFF = 1024 + 128 * ROWB; // Wf after Xs
    constexpr int TSW  = 76;                // transpose row pad (floats)

    extern __shared__ __align__(16) char sm[];
    float* ca   = (float*)sm;               // [64] bn scale (MODE 1)
    float* cb   = ca + 64;                  // [64] bn shift
    float* sred = (float*)(sm + 512);       // [128] block stats
    char*  Xs   = sm + 1024;
    uint32_t* WfU = (uint32_t*)(sm + WOFF);
    float* Ts   = (float*)(sm + 1024);      // transpose buf (overlaps Xs/Wf)

    int tid = threadIdx.x;
    int wid = tid >> 5, lane = tid & 31;
    int gm0 = blockIdx.x * 128;

    // ---- phase 1: consts / zero ----
    if (tid < 128) sred[tid] = 0.f;
    if (MODE == 1 && tid < 128)
        ((float*)sm)[tid] = (tid < 64) ? g_a[prevIdx][tid] : g_c[prevIdx][tid - 64];
    if (MODE == 0) {
        uint4 z = make_uint4(0, 0, 0, 0);
        for (int i = tid * 16; i < 128 * ROWB; i += 256 * 16) *(uint4*)(Xs + i) = z;
    }
    __syncthreads();

    // ---- phase 2a: Wf fragment table ----
    // frag(cg, s in [0,NG), g, p) = uint4 at index ((cg*NG+s)*32 + g*4+p).
    // q-th u32: row = cg*16+g+(q&1)*8, k = (s%S16)*16 + 2p + (q>>1)*8;
    // s < S16 -> hi(w), else lo(w). Pads (k >= C) are zero.
    {
        constexpr int NU = 4 * NG * 128;     // total u32
        for (int i = tid; i < NU; i += 256) {
            int q = i & 3, p = (i >> 2) & 3, g = (i >> 4) & 7;
            int t2 = i >> 7;
            int s = t2 % NG, cg = t2 / NG;
            int row = cg * 16 + g + (q & 1) * 8;
            int k = (s % S16) * 16 + 2 * p + ((q >> 1) & 1) * 8;
            bool lo = (s >= S16);
            uint32_t v = 0;
            if (k < C) {
                __nv_bfloat16 h0, l0; split2(W[row * C + k], h0, l0);
                v = lo ? bfbits(l0) : bfbits(h0);
            }
            if (k + 1 < C) {
                __nv_bfloat16 h1, l1; split2(W[row * C + k + 1], h1, l1);
                v |= (uint32_t)(lo ? bfbits(l1) : bfbits(h1)) << 16;
            }
            WfU[i] = v;
        }
    }

    // ---- phase 2b: X build (hi groups 0..S16-1, lo groups S16..NG-1) ----
    {
        int m = tid >> 1, h = tid & 1;
        int gm = gm0 + m;
        char* rowp = Xs + m * ROWB;
        if (MODE == 0) {
            int b = gm >> 14, mloc = gm & 16383;
            int n = mloc >> 4;
            int ng = g_topidx[gm];
            const float* Fb = F + (size_t)b * CIN * NN;
            #pragma unroll
            for (int blk2 = 0; blk2 < 2; blk2++) {
                __nv_bfloat16 hi[16], lo[16];
                #pragma unroll
                for (int j = 0; j < 16; j++) {
                    int c = blk2 * 16 + j;
                    float xi = Fb[c * NN + n];
                    float v = h ? (Fb[c * NN + ng] - xi) : xi;
                    int pi = pidx(j);
                    split2(v, hi[pi], lo[pi]);
                }
                int gidx = h * 2 + blk2;            // k-group of c (k = h*32+blk2*16+j)
                st32(rowp + gidx * 32, hi);
                st32(rowp + (S16 + gidx) * 32, lo);
            }
            if (h == 1) {   // edge features k=64..67 -> group 4 (hi), 9 (lo)
                __nv_bfloat16 eh[4], el[4];
                #pragma unroll
                for (int e = 0; e < 4; e++) {
                    float v = g_eft[(b * EIN + e) * (NN * KK) + mloc];
                    split2(v, eh[e], el[e]);
                }
                uint32_t h01 = (uint32_t)bfbits(eh[0]) | ((uint32_t)bfbits(eh[1]) << 16);
                uint32_t h23 = (uint32_t)bfbits(eh[2]) | ((uint32_t)bfbits(eh[3]) << 16);
                uint32_t l01 = (uint32_t)bfbits(el[0]) | ((uint32_t)bfbits(el[1]) << 16);
                uint32_t l23 = (uint32_t)bfbits(el[2]) | ((uint32_t)bfbits(el[3]) << 16);
                *(uint32_t*)(rowp + 4 * 32)     = h01;  *(uint32_t*)(rowp + 4 * 32 + 8)     = h23;
                *(uint32_t*)(rowp + (S16 + 4) * 32) = l01;  *(uint32_t*)(rowp + (S16 + 4) * 32 + 8) = l23;
            }
        } else if (MODE == 1) {
            const float4* src = (const float4*)(F + (size_t)gm * 64 + h * 32);
            float4 v[8];
            #pragma unroll
            for (int r = 0; r < 8; r++) v[r] = src[r];
            #pragma unroll
            for (int blk2 = 0; blk2 < 2; blk2++) {
                __nv_bfloat16 hi[16], lo[16];
                #pragma unroll
                for (int j = 0; j < 16; j++) {
                    int c = h * 32 + blk2 * 16 + j;
                    float raw = ((const float*)v)[blk2 * 16 + j];
                    float x = fmaxf(fmaf(ca[c], raw, cb[c]), 0.f);
                    int pi = pidx(j);
                    split2(x, hi[pi], lo[pi]);
                }
                int gidx = h * 2 + blk2;
                st32(rowp + gidx * 32, hi);
                st32(rowp + (S16 + gidx) * 32, lo);
            }
        } else {            // MODE 2 (shortcut, C=32)
            int b = gm >> 10, n = gm & 1023;
            __nv_bfloat16 hi[16], lo[16];
            #pragma unroll
            for (int j = 0; j < 16; j++) {
                int c = h * 16 + j;
                float v = F[(size_t)(b * CIN + c) * NN + n];
                int pi = pidx(j);
                split2(v, hi[pi], lo[pi]);
            }
            st32(rowp + h * 32, hi);
            st32(rowp + (S16 + h) * 32, lo);
        }
    }
    __syncthreads();

    // ---- phase 3: mma main loop ----
    int cg = wid & 3, mh = wid >> 2;
    int no = cg * 16;
    int g = lane >> 2, p = lane & 3;
    const uint4* WfB = (const uint4*)(sm + WOFF) + cg * NG * 32 + g * 4 + p;
    const char* xb = Xs + (mh * 64 + g) * ROWB + p * 8;

    float acc[8][4];
    #pragma unroll
    for (int ch = 0; ch < 8; ch++)
        #pragma unroll
        for (int j = 0; j < 4; j++) acc[ch][j] = 0.f;

    #pragma unroll
    for (int s = 0; s < S16; s++) {
        uint4 whi = WfB[s * 32];
        uint4 wlo = WfB[(S16 + s) * 32];
        #pragma unroll
        for (int ch = 0; ch < 8; ch++) {
            const char* bp = xb + ch * 8 * ROWB;
            uint2 bhi = *(const uint2*)(bp + s * 32);
            uint2 blo = *(const uint2*)(bp + (S16 + s) * 32);
            mma16816(acc[ch][0], acc[ch][1], acc[ch][2], acc[ch][3],
                     whi.x, whi.y, whi.z, whi.w, bhi.x, bhi.y);
            mma16816(acc[ch][0], acc[ch][1], acc[ch][2], acc[ch][3],
                     whi.x, whi.y, whi.z, whi.w, blo.x, blo.y);
            mma16816(acc[ch][0], acc[ch][1], acc[ch][2], acc[ch][3],
                     wlo.x, wlo.y, wlo.z, wlo.w, bhi.x, bhi.y);
        }
    }

    // ---- phase 4: stats (quad shuffle -> smem -> global) ----
    {
        float sA = 0.f, qA = 0.f, sB = 0.f, qB = 0.f;
        #pragma unroll
        for (int ch = 0; ch < 8; ch++) {
            sA += acc[ch][0] + acc[ch][1];
            qA += acc[ch][0] * acc[ch][0] + acc[ch][1] * acc[ch][1];
            sB += acc[ch][2] + acc[ch][3];
            qB += acc[ch][2] * acc[ch][2] + acc[ch][3] * acc[ch][3];
        }
        #pragma unroll
        for (int off = 1; off <= 2; off <<= 1) {
            sA += __shfl_xor_sync(0xffffffffu, sA, off);
            qA += __shfl_xor_sync(0xffffffffu, qA, off);
            sB += __shfl_xor_sync(0xffffffffu, sB, off);
            qB += __shfl_xor_sync(0xffffffffu, qB, off);
        }
        if (p == 0) {
            atomicAdd(&sred[no + g], sA);
            atomicAdd(&sred[64 + no + g], qA);
            atomicAdd(&sred[no + g + 8], sB);
            atomicAdd(&sred[64 + no + g + 8], qB);
        }
    }
    __syncthreads();   // sred final; Xs/Wf reads done -> Ts reuse safe

    if (tid < 64)       atomicAdd(&g_sum[statsIdx][tid], sred[tid]);
    else if (tid < 128) atomicAdd(&g_sqsum[statsIdx][tid - 64], sred[tid]);

    // ---- phase 5: transpose via smem, then contiguous [M][64] stores ----
    #pragma unroll
    for (int ch = 0; ch < 8; ch++) {
        int ml = mh * 64 + ch * 8 + 2 * p;
        Ts[ml * TSW + no + g]           = acc[ch][0];
        Ts[(ml + 1) * TSW + no + g]     = acc[ch][1];
        Ts[ml * TSW + no + g + 8]       = acc[ch][2];
        Ts[(ml + 1) * TSW + no + g + 8] = acc[ch][3];
    }
    __syncthreads();
    {
        int m = tid >> 1, h = tid & 1;
        float4* dst = (float4*)(Sout + (size_t)(gm0 + m) * 64 + h * 32);
        const float4* src = (const float4*)((const char*)Ts + m * (TSW * 4) + h * 128);
        #pragma unroll
        for (int r = 0; r < 8; r++) dst[r] = src[r];
    }
}

// ------------------------------ finalize BN ---------------------------------
__global__ void k_finalize(const float* __restrict__ gamma,
                           const float* __restrict__ beta,
                           int idx, float invM) {
    int o = threadIdx.x;
    if (o < O0) {
        float m = g_sum[idx][o] * invM;
        float v = g_sqsum[idx][o] * invM - m * m;
        float a = gamma[o] / sqrtf(v + BN_EPS);
        g_a[idx][o] = a;
        g_c[idx][o] = beta[o] - m * a;
    }
}

// ------------------------------ final fuse ----------------------------------
// out[b][o][n] = relu(bn3(sc) + mean_k relu(bn2(S2)));  S2/SC are [M][64].
__global__ void k_final(const float* __restrict__ S2,
                        const float* __restrict__ SC,
                        float* __restrict__ out) {
    __shared__ __align__(16) float T[64 * 68];
    int blk = blockIdx.x;
    int b = blk >> 4;
    int n0 = (blk & 15) * 64;
    int t = threadIdx.x;
    {
        int nl = t >> 2, oq = t & 3;
        const float4* Sp  = (const float4*)(S2 + ((size_t)((b * NN + n0 + nl) * KK)) * 64 + oq * 16);
        const float4* scp = (const float4*)(SC + (size_t)(b * NN + n0 + nl) * 64 + oq * 16);
        float a2[16], c2[16], a3[16], c3[16];
        #pragma unroll
        for (int j = 0; j < 16; j++) {
            int o = oq * 16 + j;
            a2[j] = g_a[2][o]; c2[j] = g_c[2][o];
            a3[j] = g_a[3][o]; c3[j] = g_c[3][o];
        }
        float acc[16];
        #pragma unroll
        for (int j = 0; j < 16; j++) acc[j] = 0.f;
        for (int k = 0; k < KK; k++) {
            #pragma unroll
            for (int r = 0; r < 4; r++) {
                float4 v = Sp[k * 16 + r];
                acc[r*4+0] += fmaxf(fmaf(a2[r*4+0], v.x, c2[r*4+0]), 0.f);
                acc[r*4+1] += fmaxf(fmaf(a2[r*4+1], v.y, c2[r*4+1]), 0.f);
                acc[r*4+2] += fmaxf(fmaf(a2[r*4+2], v.z, c2[r*4+2]), 0.f);
                acc[r*4+3] += fmaxf(fmaf(a2[r*4+3], v.w, c2[r*4+3]), 0.f);
            }
        }
        #pragma unroll
        for (int r = 0; r < 4; r++) {
            float4 sv = scp[r];
            float sc4[4] = {sv.x, sv.y, sv.z, sv.w};
            #pragma unroll
            for (int j2 = 0; j2 < 4; j2++) {
                int j = r * 4 + j2;
                float res = fmaxf(fmaf(a3[j], sc4[j2], c3[j]) + acc[j] * (1.f / KK), 0.f);
                T[(oq * 16 + j) * 68 + nl] = res;
            }
        }
    }
    __syncthreads();
    {
        int o = t >> 2, part = t & 3;
        const float4* tp = (const float4*)(T + o * 68 + part * 16);
        float4* op = (float4*)(out + (size_t)b * (O0 * NN) + o * NN + n0 + part * 16);
        #pragma unroll
        for (int r = 0; r < 4; r++) op[r] = tp[r];
    }
}

// ------------------------------- launch -------------------------------------
extern "C" void kernel_launch(void* const* d_in, const int* in_sizes, int n_in,
                              void* d_out, int out_size) {
    const float* points    = (const float*)d_in[0];
    const float* features  = (const float*)d_in[1];
    const int*   edge_list = (const int*)d_in[2];
    const float* edge_feat = (const float*)d_in[3];
    int base = (n_in >= 17 && in_sizes[4] == 1) ? 5 : 4;
    const float* W0   = (const float*)d_in[base + 0];
    const float* W1   = (const float*)d_in[base + 1];
    const float* W2   = (const float*)d_in[base + 2];
    const float* g0   = (const float*)d_in[base + 3];
    const float* b0   = (const float*)d_in[base + 4];
    const float* g1   = (const float*)d_in[base + 5];
    const float* b1   = (const float*)d_in[base + 6];
    const float* g2   = (const float*)d_in[base + 7];
    const float* b2   = (const float*)d_in[base + 8];
    const float* sc_w = (const float*)d_in[base + 9];
    const float* sc_g = (const float*)d_in[base + 10];
    const float* sc_b = (const float*)d_in[base + 11];

    void *pS0, *pS1, *pSC;
    cudaGetSymbolAddress(&pS0, g_S0);
    cudaGetSymbolAddress(&pS1, g_S1);
    cudaGetSymbolAddress(&pSC, g_scb);
    float* S0 = (float*)pS0;
    float* S1 = (float*)pS1;
    float* SC = (float*)pSC;

    // smem sizes: max(Xs+Wf, transpose buf 1024+128*76*4=39936)
    const int TS_MIN = 1024 + 128 * 76 * 4;                        // 39936
    const int smem0  = 1024 + 128 * 352 + 4 * 10 * 32 * 16;        // 66560
    const int smem1  = 1024 + 128 * 288 + 4 * 8 * 32 * 16;         // 54272
    int smemSC = 1024 + 128 * 160 + 4 * 4 * 32 * 16;               // 29696
    if (smemSC < TS_MIN) smemSC = TS_MIN;                          // 39936
    cudaFuncSetAttribute(k_gemm<68, 0>, cudaFuncAttributeMaxDynamicSharedMemorySize, smem0);
    cudaFuncSetAttribute(k_gemm<64, 1>, cudaFuncAttributeMaxDynamicSharedMemorySize, smem1);
    cudaFuncSetAttribute(k_gemm<32, 2>, cudaFuncAttributeMaxDynamicSharedMemorySize, smemSC);

    k_init<<<512, 256>>>();
    k_scatter<<<(BB * PP + 255) / 256, 256>>>(edge_list, edge_feat);
    k_fb<<<(BB * NN + 255) / 256, 256>>>();
    k_knn<<<64, 128>>>(points);

    k_gemm<32, 2><<<M_SC / 128, 256, smemSC>>>(sc_w, features, SC, 3, 0);
    k_gemm<68, 0><<<M_ALL / 128, 256, smem0>>>(W0, features, S0, 0, 0);
    k_finalize<<<1, 64>>>(g0, b0, 0, 1.f / (float)M_ALL);
    k_gemm<64, 1><<<M_ALL / 128, 256, smem1>>>(W1, S0, S1, 1, 0);
    k_finalize<<<1, 64>>>(g1, b1, 1, 1.f / (float)M_ALL);
    k_gemm<64, 1><<<M_ALL / 128, 256, smem1>>>(W2, S1, S0, 2, 1);
    k_finalize<<<1, 64>>>(g2, b2, 2, 1.f / (float)M_ALL);
    k_finalize<<<1, 64>>>(sc_g, sc_b, 3, 1.f / (float)M_SC);

    k_final<<<BB * 16, 256>>>(S0, SC, (float*)d_out);
}

// round 8
// speedup vs baseline: 1.2790x; 1.2790x over previous
#include <cuda_runtime.h>
#include <cuda_bf16.h>
#include <math.h>
#include <stdint.h>

// ---------------------------------------------------------------------------
// EdgeFeatureConvBlock  (B=32, N=1024, P=8192, K=16, C_IN=32, E_IN=4, OUT=64)
// R8 (= R7 resubmit after infra failure): R5 base + single change: X smem
//     holds only [hi|lo] (no duplicated hi segment); the third product
//     w_lo*x_hi reuses the already-loaded b_hi fragment. Same arithmetic,
//     33% fewer LDS + smaller build/zero-fill, A-hoist 60->40 regs.
// ---------------------------------------------------------------------------

#define BB   32
#define NN   1024
#define PP   8192
#define KK   16
#define CIN  32
#define EIN  4
#define O0   64
#define M_ALL (BB*NN*KK) // 524288
#define M_SC  (BB*NN)    // 32768
#define BN_EPS 1e-5f

// ------------------------- scratch (device globals) ------------------------
__device__ float g_S0[(size_t)O0 * M_ALL];   // [64][M]
__device__ float g_S1[(size_t)O0 * M_ALL];
__device__ float g_scb[(size_t)O0 * M_SC];
__device__ int   g_topidx[M_ALL];
__device__ float g_eft[BB * EIN * NN * KK];
__device__ float g_sum[4][O0];
__device__ float g_sqsum[4][O0];
__device__ float g_a[4][O0];
__device__ float g_c[4][O0];
__device__ int   g_fb_list[BB * NN];
__device__ int   g_fb_count;

// ------------------------------ helpers -------------------------------------
__device__ __forceinline__ void split2(float x, __nv_bfloat16& h, __nv_bfloat16& l) {
    h = __float2bfloat16_rn(x);
    l = __float2bfloat16_rn(x - __bfloat162float(h));
}
__device__ __forceinline__ uint16_t bfbits(__nv_bfloat16 v) {
    return *(uint16_t*)&v;
}
// u16-index inside a 32B k-group for element j (0..15):
// order [0,1,8,9, 2,3,10,11, 4,5,12,13, 6,7,14,15]
__device__ __forceinline__ int pidx(int j) {
    return ((j & 6) << 1) | ((j & 8) >> 2) | (j & 1);
}
__device__ __forceinline__ void st32(char* p, const __nv_bfloat16* v) {
    *(uint4*)p        = ((const uint4*)v)[0];
    *(uint4*)(p + 16) = ((const uint4*)v)[1];
}
__device__ __forceinline__ void mma16816(float& d0, float& d1, float& d2, float& d3,
                                         uint32_t a0, uint32_t a1, uint32_t a2, uint32_t a3,
                                         uint32_t b0, uint32_t b1) {
    asm volatile(
        "mma.sync.aligned.m16n8k16.row.col.f32.bf16.bf16.f32 "
        "{%0,%1,%2,%3}, {%4,%5,%6,%7}, {%8,%9}, {%0,%1,%2,%3};"
        : "+f"(d0), "+f"(d1), "+f"(d2), "+f"(d3)
        : "r"(a0), "r"(a1), "r"(a2), "r"(a3), "r"(b0), "r"(b1));
}

// ------------------------------- init ---------------------------------------
__global__ void k_init() {
    int i = blockIdx.x * blockDim.x + threadIdx.x;
    int stride = gridDim.x * blockDim.x;
    for (int j = i; j < M_ALL; j += stride) g_topidx[j] = NN - 1;
    for (int j = i; j < BB * EIN * NN * KK; j += stride) g_eft[j] = 0.f;
    if (i < O0) {
        #pragma unroll
        for (int l = 0; l < 4; l++) { g_sum[l][i] = 0.f; g_sqsum[l][i] = 0.f; }
    }
    if (i == 0) g_fb_count = 0;
}

// ------------------------------ edge scatter --------------------------------
__global__ void k_scatter(const int* __restrict__ edge_list,
                          const float* __restrict__ edge_feat) {
    int t = blockIdx.x * blockDim.x + threadIdx.x;
    if (t >= BB * PP) return;
    int b = t / PP, p = t % PP;
    const int* src = edge_list + (size_t)b * 2 * PP;
    const int* dst = src + PP;
    int s = src[p];
    int lo = 0, hi = p;
    while (lo < hi) { int mid = (lo + hi) >> 1; if (src[mid] < s) lo = mid + 1; else hi = mid; }
    int rank = p - lo;
    if (rank < KK) {
        g_topidx[(b * NN + s) * KK + rank] = dst[p];
        #pragma unroll
        for (int e = 0; e < EIN; e++)
            g_eft[((b * EIN + e) * NN + s) * KK + rank] =
                edge_feat[((size_t)b * EIN + e) * PP + p];
    }
}

// --------------------------- fallback detection -----------------------------
__global__ void k_fb() {
    int t = blockIdx.x * blockDim.x + threadIdx.x;
    if (t >= BB * NN) return;
    if (g_topidx[t * KK] == NN - 1) {
        int pos = atomicAdd(&g_fb_count, 1);
        g_fb_list[pos] = t;
    }
}

// ------------------------------- knn (fallback rows only) -------------------
__global__ void k_knn(const float* __restrict__ points) {
    __shared__ float pd[NN];
    __shared__ float swv[4];
    __shared__ int   swi[4];
    int nfb = g_fb_count;
    for (int e = blockIdx.x; e < nfb; e += gridDim.x) {
        int bn = g_fb_list[e];
        int b = bn / NN, n = bn % NN;
        const float* px = points + (size_t)b * 2 * NN;
        const float* py = px + NN;
        float pxn = px[n], pyn = py[n];
        float xxn = pxn * pxn + pyn * pyn;
        for (int m = threadIdx.x; m < NN; m += blockDim.x) {
            float xm = px[m], ym = py[m];
            float inner = -2.0f * (pxn * xm + pyn * ym);
            float xxm = xm * xm + ym * ym;
            float v = -xxn - inner - xxm;
            pd[m] = (m == n) ? -INFINITY : v;
        }
        __syncthreads();
        for (int kk = 0; kk < KK; kk++) {
            float bv = -INFINITY; int bi = NN;
            for (int m = threadIdx.x; m < NN; m += blockDim.x) {
                float v = pd[m];
                if (v > bv) { bv = v; bi = m; }
            }
            #pragma unroll
            for (int off = 16; off; off >>= 1) {
                float ov = __shfl_down_sync(0xffffffffu, bv, off);
                int   oi = __shfl_down_sync(0xffffffffu, bi, off);
                if (ov > bv || (ov == bv && oi < bi)) { bv = ov; bi = oi; }
            }
            if ((threadIdx.x & 31) == 0) { swv[threadIdx.x >> 5] = bv; swi[threadIdx.x >> 5] = bi; }
            __syncthreads();
            if (threadIdx.x == 0) {
                float fv = swv[0]; int fi = swi[0];
                #pragma unroll
                for (int w = 1; w < 4; w++)
                    if (swv[w] > fv || (swv[w] == fv && swi[w] < fi)) { fv = swv[w]; fi = swi[w]; }
                g_topidx[bn * KK + kk] = fi;
                pd[fi] = -INFINITY;
            }
            __syncthreads();
        }
        __syncthreads();
    }
}

// --------------------------- mma GEMM + BN stats -----------------------------
// Sout[64][M] = W[64][C] * X[C][M].  X smem = [x_hi | x_lo] (NG = 2*S16
// k-groups). Per k-group s: mma(whi,xhi) + mma(whi,xlo) + mma(wlo,xhi).
// CTA: 128 columns (m), 256 threads = 8 warps = 4 channel-groups x 2 m-halves.
// Warp: W fragments (hi+lo) hoisted in regs; loops 8 chunks of 8 m-cols.
// MODE: 0 = gather-build 68ch, 1 = relu(bn(Sin)), 2 = features (shortcut).
template<int C, int MODE>
__global__ __launch_bounds__(256, 2) void k_gemm(
    const float* __restrict__ W,
    const float* __restrict__ F,
    float* __restrict__ Sout,
    int statsIdx, int prevIdx, int Mtot)
{
    constexpr int SEG  = (C + 15) & ~15;     // 80 / 64 / 32
    constexpr int S16  = SEG / 16;           // 5 / 4 / 2
    constexpr int NG   = 2 * S16;            // 10 / 8 / 4 k-groups in X
    constexpr int RB0  = NG * 32;
    constexpr int ROWB = RB0 + (((RB0 % 128) == 32 || (RB0 % 128) == 96) ? 0 : 32);
    constexpr int XOFF = 1024;
    constexpr int WOFF = XOFF + 128 * ROWB;

    extern __shared__ __align__(16) char sm[];
    float* ca   = (float*)sm;            // [64] bn scale
    float* cb   = ca + 64;               // [64] bn shift
    float* sred = cb + 64;               // [128] block stats (sum | sqsum)
    char*  Xs   = sm + XOFF;
    char*  Ws   = sm + WOFF;

    int tid = threadIdx.x;
    int wid = tid >> 5, lane = tid & 31;
    int gm0 = blockIdx.x * 128;

    // ---- phase 1: zero / consts ----
    if (tid < 128) sred[tid] = 0.f;
    if (MODE == 1 && tid < 128)
        ((float*)sm)[tid] = (tid < 64) ? g_a[prevIdx][tid] : g_c[prevIdx][tid - 64];
    {   // zero W staging always; zero X only when padding exists (MODE 0)
        uint4 z = make_uint4(0, 0, 0, 0);
        for (int i = tid * 16; i < 64 * ROWB; i += 256 * 16) *(uint4*)(Ws + i) = z;
        if (MODE == 0)
            for (int i = tid * 16; i < 128 * ROWB; i += 256 * 16) *(uint4*)(Xs + i) = z;
    }
    __syncthreads();

    // ---- phase 2a: W build (hi groups 0..S16-1, lo groups S16..NG-1) ----
    for (int i = tid; i < 64 * C; i += 256) {
        int o = i / C, c = i % C;
        float w = W[i];
        __nv_bfloat16 wh, wl; split2(w, wh, wl);
        char* row = Ws + o * ROWB;
        int g = c >> 4, pj = pidx(c & 15) * 2;
        *(__nv_bfloat16*)(row + g * 32 + pj) = wh;
        *(__nv_bfloat16*)(row + (S16 + g) * 32 + pj) = wl;
    }

    // ---- phase 2b: X build ----
    {
        int m = tid >> 1, h = tid & 1;
        int gm = gm0 + m;
        char* rowp = Xs + m * ROWB;
        if (MODE == 0) {
            int b = gm >> 14, mloc = gm & 16383;
            int n = mloc >> 4;
            int ng = g_topidx[gm];
            const float* Fb = F + (size_t)b * CIN * NN;
            #pragma unroll
            for (int blk2 = 0; blk2 < 2; blk2++) {
                __nv_bfloat16 hi[16], lo[16];
                #pragma unroll
                for (int j = 0; j < 16; j++) {
                    int c = blk2 * 16 + j;
                    float xi = Fb[c * NN + n];
                    float v = h ? (Fb[c * NN + ng] - xi) : xi;
                    int pi = pidx(j);
                    split2(v, hi[pi], lo[pi]);
                }
                int gidx = h * 2 + blk2;        // k = h*32 + blk2*16 + j
                st32(rowp + gidx * 32, hi);
                st32(rowp + (S16 + gidx) * 32, lo);
            }
            if (h == 1) {   // edge features k=64..67 -> hi group 4, lo group S16+4
                __nv_bfloat16 eh[4], el[4];
                #pragma unroll
                for (int e = 0; e < 4; e++) {
                    float v = g_eft[(b * EIN + e) * (NN * KK) + mloc];
                    split2(v, eh[e], el[e]);
                }
                uint32_t h01 = (uint32_t)bfbits(eh[0]) | ((uint32_t)bfbits(eh[1]) << 16);
                uint32_t h23 = (uint32_t)bfbits(eh[2]) | ((uint32_t)bfbits(eh[3]) << 16);
                uint32_t l01 = (uint32_t)bfbits(el[0]) | ((uint32_t)bfbits(el[1]) << 16);
                uint32_t l23 = (uint32_t)bfbits(el[2]) | ((uint32_t)bfbits(el[3]) << 16);
                *(uint32_t*)(rowp + 4 * 32)     = h01;
                *(uint32_t*)(rowp + 4 * 32 + 8) = h23;
                *(uint32_t*)(rowp + (S16 + 4) * 32)     = l01;
                *(uint32_t*)(rowp + (S16 + 4) * 32 + 8) = l23;
            }
        } else if (MODE == 1) {
            #pragma unroll
            for (int blk2 = 0; blk2 < 2; blk2++) {
                __nv_bfloat16 hi[16], lo[16];
                #pragma unroll
                for (int j = 0; j < 16; j++) {
                    int c = h * 32 + blk2 * 16 + j;
                    float v = F[(size_t)c * Mtot + gm];
                    float x = fmaxf(fmaf(ca[c], v, cb[c]), 0.f);
                    int pi = pidx(j);
                    split2(x, hi[pi], lo[pi]);
                }
                int gidx = h * 2 + blk2;
                st32(rowp + gidx * 32, hi);
                st32(rowp + (S16 + gidx) * 32, lo);
            }
        } else {            // MODE 2 (shortcut, C=32)
            int b = gm >> 10, n = gm & 1023;
            __nv_bfloat16 hi[16], lo[16];
            #pragma unroll
            for (int j = 0; j < 16; j++) {
                int c = h * 16 + j;
                float v = F[(size_t)(b * CIN + c) * NN + n];
                int pi = pidx(j);
                split2(v, hi[pi], lo[pi]);
            }
            st32(rowp + h * 32, hi);
            st32(rowp + (S16 + h) * 32, lo);
        }
    }
    __syncthreads();

    // ---- phase 3: hoist W fragments (hi + lo) ----
    int cg = wid & 3, mh = wid >> 2;
    int no = cg * 16;
    int g = lane >> 2, p = lane & 3;
    uint2 A02[NG], A13[NG];
    #pragma unroll
    for (int s = 0; s < NG; s++) {
        A02[s] = *(uint2*)(Ws + (no + g) * ROWB + s * 32 + p * 8);
        A13[s] = *(uint2*)(Ws + (no + g + 8) * ROWB + s * 32 + p * 8);
    }

    // ---- phase 4: mma main loop ----
    float sA = 0.f, qA = 0.f, sB = 0.f, qB = 0.f;
    float* outA = Sout + (size_t)(no + g) * Mtot + gm0 + mh * 64 + 2 * p;
    float* outB = Sout + (size_t)(no + g + 8) * Mtot + gm0 + mh * 64 + 2 * p;
    #pragma unroll
    for (int ch = 0; ch < 8; ch++) {
        int m0 = mh * 64 + ch * 8;
        const char* brow = Xs + (m0 + g) * ROWB + p * 8;
        float d0 = 0.f, d1 = 0.f, d2 = 0.f, d3 = 0.f;
        #pragma unroll
        for (int s = 0; s < S16; s++) {
            uint2 bhi = *(const uint2*)(brow + s * 32);
            uint2 blo = *(const uint2*)(brow + (S16 + s) * 32);
            mma16816(d0, d1, d2, d3, A02[s].x, A13[s].x, A02[s].y, A13[s].y, bhi.x, bhi.y);
            mma16816(d0, d1, d2, d3, A02[s].x, A13[s].x, A02[s].y, A13[s].y, blo.x, blo.y);
            mma16816(d0, d1, d2, d3, A02[S16 + s].x, A13[S16 + s].x,
                     A02[S16 + s].y, A13[S16 + s].y, bhi.x, bhi.y);
        }
        *(float2*)(outA + ch * 8) = make_float2(d0, d1);
        *(float2*)(outB + ch * 8) = make_float2(d2, d3);
        sA += d0 + d1;  qA += d0 * d0 + d1 * d1;
        sB += d2 + d3;  qB += d2 * d2 + d3 * d3;
    }

    // ---- phase 5: stats reduction (quad -> smem -> global) ----
    #pragma unroll
    for (int off = 1; off <= 2; off <<= 1) {
        sA += __shfl_xor_sync(0xffffffffu, sA, off);
        qA += __shfl_xor_sync(0xffffffffu, qA, off);
        sB += __shfl_xor_sync(0xffffffffu, sB, off);
        qB += __shfl_xor_sync(0xffffffffu, qB, off);
    }
    if (p == 0) {
        atomicAdd(&sred[no + g], sA);
        atomicAdd(&sred[64 + no + g], qA);
        atomicAdd(&sred[no + g + 8], sB);
        atomicAdd(&sred[64 + no + g + 8], qB);
    }
    __syncthreads();
    if (tid < 64)        atomicAdd(&g_sum[statsIdx][tid], sred[tid]);
    else if (tid < 128)  atomicAdd(&g_sqsum[statsIdx][tid - 64], sred[tid]);
}

// ------------------------------ finalize BN ---------------------------------
__global__ void k_finalize(const float* __restrict__ gamma,
                           const float* __restrict__ beta,
                           int idx, float invM) {
    int o = threadIdx.x;
    if (o < O0) {
        float m = g_sum[idx][o] * invM;
        float v = g_sqsum[idx][o] * invM - m * m;
        float a = gamma[o] / sqrtf(v + BN_EPS);
        g_a[idx][o] = a;
        g_c[idx][o] = beta[o] - m * a;
    }
}

// ------------------------------ final fuse ----------------------------------
__global__ void k_final(float* __restrict__ out) {
    int t = blockIdx.x * blockDim.x + threadIdx.x;
    if (t >= BB * O0 * NN) return;
    int n = t & (NN - 1);
    int o = (t >> 10) & 63;
    int b = t >> 16;
    float a2 = g_a[2][o], c2 = g_c[2][o];
    const float4* S = (const float4*)(g_S0 + (size_t)o * M_ALL + b * (NN * KK) + n * KK);
    float s = 0.f;
    #pragma unroll
    for (int q = 0; q < 4; q++) {
        float4 v = S[q];
        s += fmaxf(fmaf(a2, v.x, c2), 0.f) + fmaxf(fmaf(a2, v.y, c2), 0.f)
           + fmaxf(fmaf(a2, v.z, c2), 0.f) + fmaxf(fmaf(a2, v.w, c2), 0.f);
    }
    float fts = s * (1.f / KK);
    float sc = g_scb[(size_t)o * M_SC + b * NN + n];
    float v = fmaf(g_a[3][o], sc, g_c[3][o]) + fts;
    out[t] = fmaxf(v, 0.f);
}

// ------------------------------- launch -------------------------------------
extern "C" void kernel_launch(void* const* d_in, const int* in_sizes, int n_in,
                              void* d_out, int out_size) {
    const float* points    = (const float*)d_in[0];
    const float* features  = (const float*)d_in[1];
    const int*   edge_list = (const int*)d_in[2];
    const float* edge_feat = (const float*)d_in[3];
    int base = (n_in >= 17 && in_sizes[4] == 1) ? 5 : 4;
    const float* W0   = (const float*)d_in[base + 0];
    const float* W1   = (const float*)d_in[base + 1];
    const float* W2   = (const float*)d_in[base + 2];
    const float* g0   = (const float*)d_in[base + 3];
    const float* b0   = (const float*)d_in[base + 4];
    const float* g1   = (const float*)d_in[base + 5];
    const float* b1   = (const float*)d_in[base + 6];
    const float* g2   = (const float*)d_in[base + 7];
    const float* b2   = (const float*)d_in[base + 8];
    const float* sc_w = (const float*)d_in[base + 9];
    const float* sc_g = (const float*)d_in[base + 10];
    const float* sc_b = (const float*)d_in[base + 11];

    void *pS0, *pS1, *pSC;
    cudaGetSymbolAddress(&pS0, g_S0);
    cudaGetSymbolAddress(&pS1, g_S1);
    cudaGetSymbolAddress(&pSC, g_scb);
    float* S0 = (float*)pS0;
    float* S1 = (float*)pS1;
    float* SC = (float*)pSC;

    // ROWB: layer0 352, layer1/2 288, shortcut 160
    const int smem0  = 1024 + 128 * 352 + 64 * 352;   // 68608
    const int smem1  = 1024 + 128 * 288 + 64 * 288;   // 56320
    const int smemSC = 1024 + 128 * 160 + 64 * 160;   // 31744
    cudaFuncSetAttribute(k_gemm<68, 0>, cudaFuncAttributeMaxDynamicSharedMemorySize, smem0);
    cudaFuncSetAttribute(k_gemm<64, 1>, cudaFuncAttributeMaxDynamicSharedMemorySize, smem1);
    cudaFuncSetAttribute(k_gemm<32, 2>, cudaFuncAttributeMaxDynamicSharedMemorySize, smemSC);

    k_init<<<512, 256>>>();
    k_scatter<<<(BB * PP + 255) / 256, 256>>>(edge_list, edge_feat);
    k_fb<<<(BB * NN + 255) / 256, 256>>>();
    k_knn<<<64, 128>>>(points);

    k_gemm<32, 2><<<M_SC / 128, 256, smemSC>>>(sc_w, features, SC, 3, 0, M_SC);
    k_gemm<68, 0><<<M_ALL / 128, 256, smem0>>>(W0, features, S0, 0, 0, M_ALL);
    k_finalize<<<1, 64>>>(g0, b0, 0, 1.f / (float)M_ALL);
    k_gemm<64, 1><<<M_ALL / 128, 256, smem1>>>(W1, S0, S1, 1, 0, M_ALL);
    k_finalize<<<1, 64>>>(g1, b1, 1, 1.f / (float)M_ALL);
    k_gemm<64, 1><<<M_ALL / 128, 256, smem1>>>(W2, S1, S0, 2, 1, M_ALL);
    k_finalize<<<1, 64>>>(g2, b2, 2, 1.f / (float)M_ALL);
    k_finalize<<<1, 64>>>(sc_g, sc_b, 3, 1.f / (float)M_SC);

    k_final<<<(BB * O0 * NN + 255) / 256, 256>>>((float*)d_out);
}

// round 9
// speedup vs baseline: 1.5603x; 1.2200x over previous
#include <cuda_runtime.h>
#include <cuda_bf16.h>
#include <math.h>
#include <stdint.h>

// ---------------------------------------------------------------------------
// EdgeFeatureConvBlock  (B=32, N=1024, P=8192, K=16, C_IN=32, E_IN=4, OUT=64)
// R9: R8 base (best: 477us) + single change: weight fragment tables built
//     ONCE by k_wext into global memory (L2-resident); k_gemm drops the
//     per-CTA W smem build entirely and loads fragments via cached LDG.
//     Freed smem -> 3 CTAs/SM.
// ---------------------------------------------------------------------------

#define BB   32
#define NN   1024
#define PP   8192
#define KK   16
#define CIN  32
#define EIN  4
#define O0   64
#define M_ALL (BB*NN*KK) // 524288
#define M_SC  (BB*NN)    // 32768
#define BN_EPS 1e-5f

// ------------------------- scratch (device globals) ------------------------
__device__ float g_S0[(size_t)O0 * M_ALL];   // [64][M]
__device__ float g_S1[(size_t)O0 * M_ALL];
__device__ float g_scb[(size_t)O0 * M_SC];
__device__ int   g_topidx[M_ALL];
__device__ float g_eft[BB * EIN * NN * KK];
__device__ float g_sum[4][O0];
__device__ float g_sqsum[4][O0];
__device__ float g_a[4][O0];
__device__ float g_c[4][O0];
__device__ int   g_fb_list[BB * NN];
__device__ int   g_fb_count;
// W fragment tables: [64][NG][16 u16] permuted (hi groups then lo groups)
__device__ uint16_t g_wx0[64 * 10 * 16];     // layer0: C=68, NG=10
__device__ uint16_t g_wx1[64 * 8 * 16];      // layer1: C=64, NG=8
__device__ uint16_t g_wx2[64 * 8 * 16];      // layer2: C=64, NG=8
__device__ uint16_t g_wxsc[64 * 4 * 16];     // shortcut: C=32, NG=4

// ------------------------------ helpers -------------------------------------
__device__ __forceinline__ void split2(float x, __nv_bfloat16& h, __nv_bfloat16& l) {
    h = __float2bfloat16_rn(x);
    l = __float2bfloat16_rn(x - __bfloat162float(h));
}
__device__ __forceinline__ uint16_t bfbits(__nv_bfloat16 v) {
    return *(uint16_t*)&v;
}
// u16-index inside a 32B k-group for element j (0..15):
// order [0,1,8,9, 2,3,10,11, 4,5,12,13, 6,7,14,15]
__device__ __forceinline__ int pidx(int j) {
    return ((j & 6) << 1) | ((j & 8) >> 2) | (j & 1);
}
__device__ __forceinline__ void st32(char* p, const __nv_bfloat16* v) {
    *(uint4*)p        = ((const uint4*)v)[0];
    *(uint4*)(p + 16) = ((const uint4*)v)[1];
}
__device__ __forceinline__ void mma16816(float& d0, float& d1, float& d2, float& d3,
                                         uint32_t a0, uint32_t a1, uint32_t a2, uint32_t a3,
                                         uint32_t b0, uint32_t b1) {
    asm volatile(
        "mma.sync.aligned.m16n8k16.row.col.f32.bf16.bf16.f32 "
        "{%0,%1,%2,%3}, {%4,%5,%6,%7}, {%8,%9}, {%0,%1,%2,%3};"
        : "+f"(d0), "+f"(d1), "+f"(d2), "+f"(d3)
        : "r"(a0), "r"(a1), "r"(a2), "r"(a3), "r"(b0), "r"(b1));
}

// ------------------------------- init ---------------------------------------
__global__ void k_init() {
    int i = blockIdx.x * blockDim.x + threadIdx.x;
    int stride = gridDim.x * blockDim.x;
    for (int j = i; j < M_ALL; j += stride) g_topidx[j] = NN - 1;
    for (int j = i; j < BB * EIN * NN * KK; j += stride) g_eft[j] = 0.f;
    if (i < O0) {
        #pragma unroll
        for (int l = 0; l < 4; l++) { g_sum[l][i] = 0.f; g_sqsum[l][i] = 0.f; }
    }
    if (i == 0) g_fb_count = 0;
}

// -------------------------- W fragment table build --------------------------
// One block per table. dst[o][s][16] u16; hi groups s<S16, lo groups s>=S16.
template<int C>
__global__ void k_wext(const float* __restrict__ W, uint16_t* __restrict__ dst) {
    constexpr int SEG = (C + 15) & ~15;
    constexpr int S16 = SEG / 16;
    constexpr int NG  = 2 * S16;
    int tid = threadIdx.x;
    for (int i = tid; i < 64 * NG * 16; i += 256) dst[i] = 0;
    __syncthreads();
    for (int i = tid; i < 64 * C; i += 256) {
        int o = i / C, c = i % C;
        __nv_bfloat16 wh, wl; split2(W[i], wh, wl);
        int g = c >> 4, pj = pidx(c & 15);
        dst[(o * NG + g) * 16 + pj]         = bfbits(wh);
        dst[(o * NG + S16 + g) * 16 + pj]   = bfbits(wl);
    }
}

// ------------------------------ edge scatter --------------------------------
__global__ void k_scatter(const int* __restrict__ edge_list,
                          const float* __restrict__ edge_feat) {
    int t = blockIdx.x * blockDim.x + threadIdx.x;
    if (t >= BB * PP) return;
    int b = t / PP, p = t % PP;
    const int* src = edge_list + (size_t)b * 2 * PP;
    const int* dst = src + PP;
    int s = src[p];
    int lo = 0, hi = p;
    while (lo < hi) { int mid = (lo + hi) >> 1; if (src[mid] < s) lo = mid + 1; else hi = mid; }
    int rank = p - lo;
    if (rank < KK) {
        g_topidx[(b * NN + s) * KK + rank] = dst[p];
        #pragma unroll
        for (int e = 0; e < EIN; e++)
            g_eft[((b * EIN + e) * NN + s) * KK + rank] =
                edge_feat[((size_t)b * EIN + e) * PP + p];
    }
}

// --------------------------- fallback detection -----------------------------
__global__ void k_fb() {
    int t = blockIdx.x * blockDim.x + threadIdx.x;
    if (t >= BB * NN) return;
    if (g_topidx[t * KK] == NN - 1) {
        int pos = atomicAdd(&g_fb_count, 1);
        g_fb_list[pos] = t;
    }
}

// ------------------------------- knn (fallback rows only) -------------------
__global__ void k_knn(const float* __restrict__ points) {
    __shared__ float pd[NN];
    __shared__ float swv[4];
    __shared__ int   swi[4];
    int nfb = g_fb_count;
    for (int e = blockIdx.x; e < nfb; e += gridDim.x) {
        int bn = g_fb_list[e];
        int b = bn / NN, n = bn % NN;
        const float* px = points + (size_t)b * 2 * NN;
        const float* py = px + NN;
        float pxn = px[n], pyn = py[n];
        float xxn = pxn * pxn + pyn * pyn;
        for (int m = threadIdx.x; m < NN; m += blockDim.x) {
            float xm = px[m], ym = py[m];
            float inner = -2.0f * (pxn * xm + pyn * ym);
            float xxm = xm * xm + ym * ym;
            float v = -xxn - inner - xxm;
            pd[m] = (m == n) ? -INFINITY : v;
        }
        __syncthreads();
        for (int kk = 0; kk < KK; kk++) {
            float bv = -INFINITY; int bi = NN;
            for (int m = threadIdx.x; m < NN; m += blockDim.x) {
                float v = pd[m];
                if (v > bv) { bv = v; bi = m; }
            }
            #pragma unroll
            for (int off = 16; off; off >>= 1) {
                float ov = __shfl_down_sync(0xffffffffu, bv, off);
                int   oi = __shfl_down_sync(0xffffffffu, bi, off);
                if (ov > bv || (ov == bv && oi < bi)) { bv = ov; bi = oi; }
            }
            if ((threadIdx.x & 31) == 0) { swv[threadIdx.x >> 5] = bv; swi[threadIdx.x >> 5] = bi; }
            __syncthreads();
            if (threadIdx.x == 0) {
                float fv = swv[0]; int fi = swi[0];
                #pragma unroll
                for (int w = 1; w < 4; w++)
                    if (swv[w] > fv || (swv[w] == fv && swi[w] < fi)) { fv = swv[w]; fi = swi[w]; }
                g_topidx[bn * KK + kk] = fi;
                pd[fi] = -INFINITY;
            }
            __syncthreads();
        }
        __syncthreads();
    }
}

// --------------------------- mma GEMM + BN stats -----------------------------
// Sout[64][M] = W[64][C] * X[C][M].  X smem = [x_hi | x_lo] (NG = 2*S16
// k-groups). Per k-group s: mma(whi,xhi) + mma(whi,xlo) + mma(wlo,xhi).
// W fragments come from the prebuilt global table (L2-resident).
// CTA: 128 columns (m), 256 threads = 8 warps = 4 channel-groups x 2 m-halves.
// MODE: 0 = gather-build 68ch, 1 = relu(bn(Sin)), 2 = features (shortcut).
template<int C, int MODE>
__global__ __launch_bounds__(256, 3) void k_gemm(
    const uint16_t* __restrict__ Wx,
    const float* __restrict__ F,
    float* __restrict__ Sout,
    int statsIdx, int prevIdx, int Mtot)
{
    constexpr int SEG  = (C + 15) & ~15;     // 80 / 64 / 32
    constexpr int S16  = SEG / 16;           // 5 / 4 / 2
    constexpr int NG   = 2 * S16;            // 10 / 8 / 4 k-groups in X
    constexpr int RB0  = NG * 32;
    constexpr int ROWB = RB0 + (((RB0 % 128) == 32 || (RB0 % 128) == 96) ? 0 : 32);
    constexpr int XOFF = 1024;

    extern __shared__ __align__(16) char sm[];
    float* ca   = (float*)sm;            // [64] bn scale
    float* cb   = ca + 64;               // [64] bn shift
    float* sred = cb + 64;               // [128] block stats (sum | sqsum)
    char*  Xs   = sm + XOFF;

    int tid = threadIdx.x;
    int wid = tid >> 5, lane = tid & 31;
    int gm0 = blockIdx.x * 128;

    // ---- phase 1: zero / consts ----
    if (tid < 128) sred[tid] = 0.f;
    if (MODE == 1 && tid < 128)
        ((float*)sm)[tid] = (tid < 64) ? g_a[prevIdx][tid] : g_c[prevIdx][tid - 64];
    if (MODE == 0) {   // zero X only when padding exists
        uint4 z = make_uint4(0, 0, 0, 0);
        for (int i = tid * 16; i < 128 * ROWB; i += 256 * 16) *(uint4*)(Xs + i) = z;
    }
    __syncthreads();

    // ---- phase 2: X build ----
    {
        int m = tid >> 1, h = tid & 1;
        int gm = gm0 + m;
        char* rowp = Xs + m * ROWB;
        if (MODE == 0) {
            int b = gm >> 14, mloc = gm & 16383;
            int n = mloc >> 4;
            int ng = g_topidx[gm];
            const float* Fb = F + (size_t)b * CIN * NN;
            #pragma unroll
            for (int blk2 = 0; blk2 < 2; blk2++) {
                __nv_bfloat16 hi[16], lo[16];
                #pragma unroll
                for (int j = 0; j < 16; j++) {
                    int c = blk2 * 16 + j;
                    float xi = Fb[c * NN + n];
                    float v = h ? (Fb[c * NN + ng] - xi) : xi;
                    int pi = pidx(j);
                    split2(v, hi[pi], lo[pi]);
                }
                int gidx = h * 2 + blk2;        // k = h*32 + blk2*16 + j
                st32(rowp + gidx * 32, hi);
                st32(rowp + (S16 + gidx) * 32, lo);
            }
            if (h == 1) {   // edge features k=64..67 -> hi group 4, lo group S16+4
                __nv_bfloat16 eh[4], el[4];
                #pragma unroll
                for (int e = 0; e < 4; e++) {
                    float v = g_eft[(b * EIN + e) * (NN * KK) + mloc];
                    split2(v, eh[e], el[e]);
                }
                uint32_t h01 = (uint32_t)bfbits(eh[0]) | ((uint32_t)bfbits(eh[1]) << 16);
                uint32_t h23 = (uint32_t)bfbits(eh[2]) | ((uint32_t)bfbits(eh[3]) << 16);
                uint32_t l01 = (uint32_t)bfbits(el[0]) | ((uint32_t)bfbits(el[1]) << 16);
                uint32_t l23 = (uint32_t)bfbits(el[2]) | ((uint32_t)bfbits(el[3]) << 16);
                *(uint32_t*)(rowp + 4 * 32)     = h01;
                *(uint32_t*)(rowp + 4 * 32 + 8) = h23;
                *(uint32_t*)(rowp + (S16 + 4) * 32)     = l01;
                *(uint32_t*)(rowp + (S16 + 4) * 32 + 8) = l23;
            }
        } else if (MODE == 1) {
            #pragma unroll
            for (int blk2 = 0; blk2 < 2; blk2++) {
                __nv_bfloat16 hi[16], lo[16];
                #pragma unroll
                for (int j = 0; j < 16; j++) {
                    int c = h * 32 + blk2 * 16 + j;
                    float v = F[(size_t)c * Mtot + gm];
                    float x = fmaxf(fmaf(ca[c], v, cb[c]), 0.f);
                    int pi = pidx(j);
                    split2(x, hi[pi], lo[pi]);
                }
                int gidx = h * 2 + blk2;
                st32(rowp + gidx * 32, hi);
                st32(rowp + (S16 + gidx) * 32, lo);
            }
        } else {            // MODE 2 (shortcut, C=32)
            int b = gm >> 10, n = gm & 1023;
            __nv_bfloat16 hi[16], lo[16];
            #pragma unroll
            for (int j = 0; j < 16; j++) {
                int c = h * 16 + j;
                float v = F[(size_t)(b * CIN + c) * NN + n];
                int pi = pidx(j);
                split2(v, hi[pi], lo[pi]);
            }
            st32(rowp + h * 32, hi);
            st32(rowp + (S16 + h) * 32, lo);
        }
    }

    // ---- phase 3: hoist W fragments from global table (cached) ----
    int cg = wid & 3, mh = wid >> 2;
    int no = cg * 16;
    int g = lane >> 2, p = lane & 3;
    uint2 A02[NG], A13[NG];
    #pragma unroll
    for (int s = 0; s < NG; s++) {
        A02[s] = *(const uint2*)(Wx + (no + g) * (NG * 16) + s * 16 + p * 4);
        A13[s] = *(const uint2*)(Wx + (no + g + 8) * (NG * 16) + s * 16 + p * 4);
    }
    __syncthreads();

    // ---- phase 4: mma main loop ----
    float sA = 0.f, qA = 0.f, sB = 0.f, qB = 0.f;
    float* outA = Sout + (size_t)(no + g) * Mtot + gm0 + mh * 64 + 2 * p;
    float* outB = Sout + (size_t)(no + g + 8) * Mtot + gm0 + mh * 64 + 2 * p;
    #pragma unroll
    for (int ch = 0; ch < 8; ch++) {
        int m0 = mh * 64 + ch * 8;
        const char* brow = Xs + (m0 + g) * ROWB + p * 8;
        float d0 = 0.f, d1 = 0.f, d2 = 0.f, d3 = 0.f;
        #pragma unroll
        for (int s = 0; s < S16; s++) {
            uint2 bhi = *(const uint2*)(brow + s * 32);
            uint2 blo = *(const uint2*)(brow + (S16 + s) * 32);
            mma16816(d0, d1, d2, d3, A02[s].x, A13[s].x, A02[s].y, A13[s].y, bhi.x, bhi.y);
            mma16816(d0, d1, d2, d3, A02[s].x, A13[s].x, A02[s].y, A13[s].y, blo.x, blo.y);
            mma16816(d0, d1, d2, d3, A02[S16 + s].x, A13[S16 + s].x,
                     A02[S16 + s].y, A13[S16 + s].y, bhi.x, bhi.y);
        }
        *(float2*)(outA + ch * 8) = make_float2(d0, d1);
        *(float2*)(outB + ch * 8) = make_float2(d2, d3);
        sA += d0 + d1;  qA += d0 * d0 + d1 * d1;
        sB += d2 + d3;  qB += d2 * d2 + d3 * d3;
    }

    // ---- phase 5: stats reduction (quad -> smem -> global) ----
    #pragma unroll
    for (int off = 1; off <= 2; off <<= 1) {
        sA += __shfl_xor_sync(0xffffffffu, sA, off);
        qA += __shfl_xor_sync(0xffffffffu, qA, off);
        sB += __shfl_xor_sync(0xffffffffu, sB, off);
        qB += __shfl_xor_sync(0xffffffffu, qB, off);
    }
    if (p == 0) {
        atomicAdd(&sred[no + g], sA);
        atomicAdd(&sred[64 + no + g], qA);
        atomicAdd(&sred[no + g + 8], sB);
        atomicAdd(&sred[64 + no + g + 8], qB);
    }
    __syncthreads();
    if (tid < 64)        atomicAdd(&g_sum[statsIdx][tid], sred[tid]);
    else if (tid < 128)  atomicAdd(&g_sqsum[statsIdx][tid - 64], sred[tid]);
}

// ------------------------------ finalize BN ---------------------------------
__global__ void k_finalize(const float* __restrict__ gamma,
                           const float* __restrict__ beta,
                           int idx, float invM) {
    int o = threadIdx.x;
    if (o < O0) {
        float m = g_sum[idx][o] * invM;
        float v = g_sqsum[idx][o] * invM - m * m;
        float a = gamma[o] / sqrtf(v + BN_EPS);
        g_a[idx][o] = a;
        g_c[idx][o] = beta[o] - m * a;
    }
}

// ------------------------------ final fuse ----------------------------------
__global__ void k_final(float* __restrict__ out) {
    int t = blockIdx.x * blockDim.x + threadIdx.x;
    if (t >= BB * O0 * NN) return;
    int n = t & (NN - 1);
    int o = (t >> 10) & 63;
    int b = t >> 16;
    float a2 = g_a[2][o], c2 = g_c[2][o];
    const float4* S = (const float4*)(g_S0 + (size_t)o * M_ALL + b * (NN * KK) + n * KK);
    float s = 0.f;
    #pragma unroll
    for (int q = 0; q < 4; q++) {
        float4 v = S[q];
        s += fmaxf(fmaf(a2, v.x, c2), 0.f) + fmaxf(fmaf(a2, v.y, c2), 0.f)
           + fmaxf(fmaf(a2, v.z, c2), 0.f) + fmaxf(fmaf(a2, v.w, c2), 0.f);
    }
    float fts = s * (1.f / KK);
    float sc = g_scb[(size_t)o * M_SC + b * NN + n];
    float v = fmaf(g_a[3][o], sc, g_c[3][o]) + fts;
    out[t] = fmaxf(v, 0.f);
}

// ------------------------------- launch -------------------------------------
extern "C" void kernel_launch(void* const* d_in, const int* in_sizes, int n_in,
                              void* d_out, int out_size) {
    const float* points    = (const float*)d_in[0];
    const float* features  = (const float*)d_in[1];
    const int*   edge_list = (const int*)d_in[2];
    const float* edge_feat = (const float*)d_in[3];
    int base = (n_in >= 17 && in_sizes[4] == 1) ? 5 : 4;
    const float* W0   = (const float*)d_in[base + 0];
    const float* W1   = (const float*)d_in[base + 1];
    const float* W2   = (const float*)d_in[base + 2];
    const float* g0   = (const float*)d_in[base + 3];
    const float* b0   = (const float*)d_in[base + 4];
    const float* g1   = (const float*)d_in[base + 5];
    const float* b1   = (const float*)d_in[base + 6];
    const float* g2   = (const float*)d_in[base + 7];
    const float* b2   = (const float*)d_in[base + 8];
    const float* sc_w = (const float*)d_in[base + 9];
    const float* sc_g = (const float*)d_in[base + 10];
    const float* sc_b = (const float*)d_in[base + 11];

    void *pS0, *pS1, *pSC, *pW0, *pW1, *pW2, *pWS;
    cudaGetSymbolAddress(&pS0, g_S0);
    cudaGetSymbolAddress(&pS1, g_S1);
    cudaGetSymbolAddress(&pSC, g_scb);
    cudaGetSymbolAddress(&pW0, g_wx0);
    cudaGetSymbolAddress(&pW1, g_wx1);
    cudaGetSymbolAddress(&pW2, g_wx2);
    cudaGetSymbolAddress(&pWS, g_wxsc);
    float* S0 = (float*)pS0;
    float* S1 = (float*)pS1;
    float* SC = (float*)pSC;

    // smem: 1024 ctrl + Xs (ROWB: layer0 352, layer1/2 288, shortcut 160)
    const int smem0  = 1024 + 128 * 352;   // 46080
    const int smem1  = 1024 + 128 * 288;   // 37888
    const int smemSC = 1024 + 128 * 160;   // 21504
    cudaFuncSetAttribute(k_gemm<68, 0>, cudaFuncAttributeMaxDynamicSharedMemorySize, smem0);
    cudaFuncSetAttribute(k_gemm<64, 1>, cudaFuncAttributeMaxDynamicSharedMemorySize, smem1);
    cudaFuncSetAttribute(k_gemm<32, 2>, cudaFuncAttributeMaxDynamicSharedMemorySize, smemSC);

    k_init<<<512, 256>>>();
    k_wext<68><<<1, 256>>>(W0, (uint16_t*)pW0);
    k_wext<64><<<1, 256>>>(W1, (uint16_t*)pW1);
    k_wext<64><<<1, 256>>>(W2, (uint16_t*)pW2);
    k_wext<32><<<1, 256>>>(sc_w, (uint16_t*)pWS);
    k_scatter<<<(BB * PP + 255) / 256, 256>>>(edge_list, edge_feat);
    k_fb<<<(BB * NN + 255) / 256, 256>>>();
    k_knn<<<64, 128>>>(points);

    k_gemm<32, 2><<<M_SC / 128, 256, smemSC>>>((const uint16_t*)pWS, features, SC, 3, 0, M_SC);
    k_gemm<68, 0><<<M_ALL / 128, 256, smem0>>>((const uint16_t*)pW0, features, S0, 0, 0, M_ALL);
    k_finalize<<<1, 64>>>(g0, b0, 0, 1.f / (float)M_ALL);
    k_gemm<64, 1><<<M_ALL / 128, 256, smem1>>>((const uint16_t*)pW1, S0, S1, 1, 0, M_ALL);
    k_finalize<<<1, 64>>>(g1, b1, 1, 1.f / (float)M_ALL);
    k_gemm<64, 1><<<M_ALL / 128, 256, smem1>>>((const uint16_t*)pW2, S1, S0, 2, 1, M_ALL);
    k_finalize<<<1, 64>>>(g2, b2, 2, 1.f / (float)M_ALL);
    k_finalize<<<1, 64>>>(sc_g, sc_b, 3, 1.f / (float)M_SC);

    k_final<<<(BB * O0 * NN + 255) / 256, 256>>>((float*)d_out);
}

// round 10
// speedup vs baseline: 1.6653x; 1.0673x over previous
#include <cuda_runtime.h>
#include <cuda_bf16.h>
#include <math.h>
#include <stdint.h>

// ---------------------------------------------------------------------------
// EdgeFeatureConvBlock  (B=32, N=1024, P=8192, K=16, C_IN=32, E_IN=4, OUT=64)
// R10: R9 base (best: 391us) + prep-chain collapse: the 4 serial k_wext
//      launches (11us each, grid=1, latency-bound) and k_init merged into ONE
//      k_prep kernel (blocks 0-3 build W tables concurrently, blocks 4+ do
//      init). finalize(2)+finalize(3) merged. GEMMs byte-identical to R9.
// ---------------------------------------------------------------------------

#define BB   32
#define NN   1024
#define PP   8192
#define KK   16
#define CIN  32
#define EIN  4
#define O0   64
#define M_ALL (BB*NN*KK) // 524288
#define M_SC  (BB*NN)    // 32768
#define BN_EPS 1e-5f

// ------------------------- scratch (device globals) ------------------------
__device__ float g_S0[(size_t)O0 * M_ALL];   // [64][M]
__device__ float g_S1[(size_t)O0 * M_ALL];
__device__ float g_scb[(size_t)O0 * M_SC];
__device__ int   g_topidx[M_ALL];
__device__ float g_eft[BB * EIN * NN * KK];
__device__ float g_sum[4][O0];
__device__ float g_sqsum[4][O0];
__device__ float g_a[4][O0];
__device__ float g_c[4][O0];
__device__ int   g_fb_list[BB * NN];
__device__ int   g_fb_count;
// W fragment tables: [64][NG][16 u16] permuted (hi groups then lo groups)
__device__ uint16_t g_wx0[64 * 10 * 16];     // layer0: C=68, NG=10
__device__ uint16_t g_wx1[64 * 8 * 16];      // layer1: C=64, NG=8
__device__ uint16_t g_wx2[64 * 8 * 16];      // layer2: C=64, NG=8
__device__ uint16_t g_wxsc[64 * 4 * 16];     // shortcut: C=32, NG=4

// ------------------------------ helpers -------------------------------------
__device__ __forceinline__ void split2(float x, __nv_bfloat16& h, __nv_bfloat16& l) {
    h = __float2bfloat16_rn(x);
    l = __float2bfloat16_rn(x - __bfloat162float(h));
}
__device__ __forceinline__ uint16_t bfbits(__nv_bfloat16 v) {
    return *(uint16_t*)&v;
}
// u16-index inside a 32B k-group for element j (0..15):
// order [0,1,8,9, 2,3,10,11, 4,5,12,13, 6,7,14,15]
__device__ __forceinline__ int pidx(int j) {
    return ((j & 6) << 1) | ((j & 8) >> 2) | (j & 1);
}
__device__ __forceinline__ void st32(char* p, const __nv_bfloat16* v) {
    *(uint4*)p        = ((const uint4*)v)[0];
    *(uint4*)(p + 16) = ((const uint4*)v)[1];
}
__device__ __forceinline__ void mma16816(float& d0, float& d1, float& d2, float& d3,
                                         uint32_t a0, uint32_t a1, uint32_t a2, uint32_t a3,
                                         uint32_t b0, uint32_t b1) {
    asm volatile(
        "mma.sync.aligned.m16n8k16.row.col.f32.bf16.bf16.f32 "
        "{%0,%1,%2,%3}, {%4,%5,%6,%7}, {%8,%9}, {%0,%1,%2,%3};"
        : "+f"(d0), "+f"(d1), "+f"(d2), "+f"(d3)
        : "r"(a0), "r"(a1), "r"(a2), "r"(a3), "r"(b0), "r"(b1));
}

// --------------------- W fragment table build (device fn) -------------------
template<int C>
__device__ __forceinline__ void wext_body(const float* __restrict__ W,
                                          uint16_t* __restrict__ dst) {
    constexpr int SEG = (C + 15) & ~15;
    constexpr int S16 = SEG / 16;
    constexpr int NG  = 2 * S16;
    int tid = threadIdx.x;
    for (int i = tid; i < 64 * NG * 16; i += 256) dst[i] = 0;
    __syncthreads();
    for (int i = tid; i < 64 * C; i += 256) {
        int o = i / C, c = i % C;
        __nv_bfloat16 wh, wl; split2(W[i], wh, wl);
        int g = c >> 4, pj = pidx(c & 15);
        dst[(o * NG + g) * 16 + pj]       = bfbits(wh);
        dst[(o * NG + S16 + g) * 16 + pj] = bfbits(wl);
    }
}

// ------------------- prep: W tables (blocks 0-3) + init (4+) ----------------
__global__ void k_prep(const float* __restrict__ W0, const float* __restrict__ W1,
                       const float* __restrict__ W2, const float* __restrict__ Wsc) {
    int blk = blockIdx.x;
    if (blk == 0)      { wext_body<68>(W0,  g_wx0);  return; }
    else if (blk == 1) { wext_body<64>(W1,  g_wx1);  return; }
    else if (blk == 2) { wext_body<64>(W2,  g_wx2);  return; }
    else if (blk == 3) { wext_body<32>(Wsc, g_wxsc); return; }
    int i = (blk - 4) * blockDim.x + threadIdx.x;
    int stride = (gridDim.x - 4) * blockDim.x;
    for (int j = i; j < M_ALL; j += stride) g_topidx[j] = NN - 1;
    for (int j = i; j < BB * EIN * NN * KK; j += stride) g_eft[j] = 0.f;
    if (i < O0) {
        #pragma unroll
        for (int l = 0; l < 4; l++) { g_sum[l][i] = 0.f; g_sqsum[l][i] = 0.f; }
    }
    if (i == 0) g_fb_count = 0;
}

// ------------------------------ edge scatter --------------------------------
__global__ void k_scatter(const int* __restrict__ edge_list,
                          const float* __restrict__ edge_feat) {
    int t = blockIdx.x * blockDim.x + threadIdx.x;
    if (t >= BB * PP) return;
    int b = t / PP, p = t % PP;
    const int* src = edge_list + (size_t)b * 2 * PP;
    const int* dst = src + PP;
    int s = src[p];
    int lo = 0, hi = p;
    while (lo < hi) { int mid = (lo + hi) >> 1; if (src[mid] < s) lo = mid + 1; else hi = mid; }
    int rank = p - lo;
    if (rank < KK) {
        g_topidx[(b * NN + s) * KK + rank] = dst[p];
        #pragma unroll
        for (int e = 0; e < EIN; e++)
            g_eft[((b * EIN + e) * NN + s) * KK + rank] =
                edge_feat[((size_t)b * EIN + e) * PP + p];
    }
}

// --------------------------- fallback detection -----------------------------
__global__ void k_fb() {
    int t = blockIdx.x * blockDim.x + threadIdx.x;
    if (t >= BB * NN) return;
    if (g_topidx[t * KK] == NN - 1) {
        int pos = atomicAdd(&g_fb_count, 1);
        g_fb_list[pos] = t;
    }
}

// ------------------------------- knn (fallback rows only) -------------------
__global__ void k_knn(const float* __restrict__ points) {
    __shared__ float pd[NN];
    __shared__ float swv[4];
    __shared__ int   swi[4];
    int nfb = g_fb_count;
    for (int e = blockIdx.x; e < nfb; e += gridDim.x) {
        int bn = g_fb_list[e];
        int b = bn / NN, n = bn % NN;
        const float* px = points + (size_t)b * 2 * NN;
        const float* py = px + NN;
        float pxn = px[n], pyn = py[n];
        float xxn = pxn * pxn + pyn * pyn;
        for (int m = threadIdx.x; m < NN; m += blockDim.x) {
            float xm = px[m], ym = py[m];
            float inner = -2.0f * (pxn * xm + pyn * ym);
            float xxm = xm * xm + ym * ym;
            float v = -xxn - inner - xxm;
            pd[m] = (m == n) ? -INFINITY : v;
        }
        __syncthreads();
        for (int kk = 0; kk < KK; kk++) {
            float bv = -INFINITY; int bi = NN;
            for (int m = threadIdx.x; m < NN; m += blockDim.x) {
                float v = pd[m];
                if (v > bv) { bv = v; bi = m; }
            }
            #pragma unroll
            for (int off = 16; off; off >>= 1) {
                float ov = __shfl_down_sync(0xffffffffu, bv, off);
                int   oi = __shfl_down_sync(0xffffffffu, bi, off);
                if (ov > bv || (ov == bv && oi < bi)) { bv = ov; bi = oi; }
            }
            if ((threadIdx.x & 31) == 0) { swv[threadIdx.x >> 5] = bv; swi[threadIdx.x >> 5] = bi; }
            __syncthreads();
            if (threadIdx.x == 0) {
                float fv = swv[0]; int fi = swi[0];
                #pragma unroll
                for (int w = 1; w < 4; w++)
                    if (swv[w] > fv || (swv[w] == fv && swi[w] < fi)) { fv = swv[w]; fi = swi[w]; }
                g_topidx[bn * KK + kk] = fi;
                pd[fi] = -INFINITY;
            }
            __syncthreads();
        }
        __syncthreads();
    }
}

// --------------------------- mma GEMM + BN stats -----------------------------
// Sout[64][M] = W[64][C] * X[C][M].  X smem = [x_hi | x_lo] (NG = 2*S16
// k-groups). Per k-group s: mma(whi,xhi) + mma(whi,xlo) + mma(wlo,xhi).
// W fragments come from the prebuilt global table (L2-resident).
// CTA: 128 columns (m), 256 threads = 8 warps = 4 channel-groups x 2 m-halves.
// MODE: 0 = gather-build 68ch, 1 = relu(bn(Sin)), 2 = features (shortcut).
template<int C, int MODE>
__global__ __launch_bounds__(256, 3) void k_gemm(
    const uint16_t* __restrict__ Wx,
    const float* __restrict__ F,
    float* __restrict__ Sout,
    int statsIdx, int prevIdx, int Mtot)
{
    constexpr int SEG  = (C + 15) & ~15;     // 80 / 64 / 32
    constexpr int S16  = SEG / 16;           // 5 / 4 / 2
    constexpr int NG   = 2 * S16;            // 10 / 8 / 4 k-groups in X
    constexpr int RB0  = NG * 32;
    constexpr int ROWB = RB0 + (((RB0 % 128) == 32 || (RB0 % 128) == 96) ? 0 : 32);
    constexpr int XOFF = 1024;

    extern __shared__ __align__(16) char sm[];
    float* ca   = (float*)sm;            // [64] bn scale
    float* cb   = ca + 64;               // [64] bn shift
    float* sred = cb + 64;               // [128] block stats (sum | sqsum)
    char*  Xs   = sm + XOFF;

    int tid = threadIdx.x;
    int wid = tid >> 5, lane = tid & 31;
    int gm0 = blockIdx.x * 128;

    // ---- phase 1: zero / consts ----
    if (tid < 128) sred[tid] = 0.f;
    if (MODE == 1 && tid < 128)
        ((float*)sm)[tid] = (tid < 64) ? g_a[prevIdx][tid] : g_c[prevIdx][tid - 64];
    if (MODE == 0) {   // zero X only when padding exists
        uint4 z = make_uint4(0, 0, 0, 0);
        for (int i = tid * 16; i < 128 * ROWB; i += 256 * 16) *(uint4*)(Xs + i) = z;
    }
    __syncthreads();

    // ---- phase 2: X build ----
    {
        int m = tid >> 1, h = tid & 1;
        int gm = gm0 + m;
        char* rowp = Xs + m * ROWB;
        if (MODE == 0) {
            int b = gm >> 14, mloc = gm & 16383;
            int n = mloc >> 4;
            int ng = g_topidx[gm];
            const float* Fb = F + (size_t)b * CIN * NN;
            #pragma unroll
            for (int blk2 = 0; blk2 < 2; blk2++) {
                __nv_bfloat16 hi[16], lo[16];
                #pragma unroll
                for (int j = 0; j < 16; j++) {
                    int c = blk2 * 16 + j;
                    float xi = Fb[c * NN + n];
                    float v = h ? (Fb[c * NN + ng] - xi) : xi;
                    int pi = pidx(j);
                    split2(v, hi[pi], lo[pi]);
                }
                int gidx = h * 2 + blk2;        // k = h*32 + blk2*16 + j
                st32(rowp + gidx * 32, hi);
                st32(rowp + (S16 + gidx) * 32, lo);
            }
            if (h == 1) {   // edge features k=64..67 -> hi group 4, lo group S16+4
                __nv_bfloat16 eh[4], el[4];
                #pragma unroll
                for (int e = 0; e < 4; e++) {
                    float v = g_eft[(b * EIN + e) * (NN * KK) + mloc];
                    split2(v, eh[e], el[e]);
                }
                uint32_t h01 = (uint32_t)bfbits(eh[0]) | ((uint32_t)bfbits(eh[1]) << 16);
                uint32_t h23 = (uint32_t)bfbits(eh[2]) | ((uint32_t)bfbits(eh[3]) << 16);
                uint32_t l01 = (uint32_t)bfbits(el[0]) | ((uint32_t)bfbits(el[1]) << 16);
                uint32_t l23 = (uint32_t)bfbits(el[2]) | ((uint32_t)bfbits(el[3]) << 16);
                *(uint32_t*)(rowp + 4 * 32)     = h01;
                *(uint32_t*)(rowp + 4 * 32 + 8) = h23;
                *(uint32_t*)(rowp + (S16 + 4) * 32)     = l01;
                *(uint32_t*)(rowp + (S16 + 4) * 32 + 8) = l23;
            }
        } else if (MODE == 1) {
            #pragma unroll
            for (int blk2 = 0; blk2 < 2; blk2++) {
                __nv_bfloat16 hi[16], lo[16];
                #pragma unroll
                for (int j = 0; j < 16; j++) {
                    int c = h * 32 + blk2 * 16 + j;
                    float v = F[(size_t)c * Mtot + gm];
                    float x = fmaxf(fmaf(ca[c], v, cb[c]), 0.f);
                    int pi = pidx(j);
                    split2(x, hi[pi], lo[pi]);
                }
                int gidx = h * 2 + blk2;
                st32(rowp + gidx * 32, hi);
                st32(rowp + (S16 + gidx) * 32, lo);
            }
        } else {            // MODE 2 (shortcut, C=32)
            int b = gm >> 10, n = gm & 1023;
            __nv_bfloat16 hi[16], lo[16];
            #pragma unroll
            for (int j = 0; j < 16; j++) {
                int c = h * 16 + j;
                float v = F[(size_t)(b * CIN + c) * NN + n];
                int pi = pidx(j);
                split2(v, hi[pi], lo[pi]);
            }
            st32(rowp + h * 32, hi);
            st32(rowp + (S16 + h) * 32, lo);
        }
    }

    // ---- phase 3: hoist W fragments from global table (cached) ----
    int cg = wid & 3, mh = wid >> 2;
    int no = cg * 16;
    int g = lane >> 2, p = lane & 3;
    uint2 A02[NG], A13[NG];
    #pragma unroll
    for (int s = 0; s < NG; s++) {
        A02[s] = *(const uint2*)(Wx + (no + g) * (NG * 16) + s * 16 + p * 4);
        A13[s] = *(const uint2*)(Wx + (no + g + 8) * (NG * 16) + s * 16 + p * 4);
    }
    __syncthreads();

    // ---- phase 4: mma main loop ----
    float sA = 0.f, qA = 0.f, sB = 0.f, qB = 0.f;
    float* outA = Sout + (size_t)(no + g) * Mtot + gm0 + mh * 64 + 2 * p;
    float* outB = Sout + (size_t)(no + g + 8) * Mtot + gm0 + mh * 64 + 2 * p;
    #pragma unroll
    for (int ch = 0; ch < 8; ch++) {
        int m0 = mh * 64 + ch * 8;
        const char* brow = Xs + (m0 + g) * ROWB + p * 8;
        float d0 = 0.f, d1 = 0.f, d2 = 0.f, d3 = 0.f;
        #pragma unroll
        for (int s = 0; s < S16; s++) {
            uint2 bhi = *(const uint2*)(brow + s * 32);
            uint2 blo = *(const uint2*)(brow + (S16 + s) * 32);
            mma16816(d0, d1, d2, d3, A02[s].x, A13[s].x, A02[s].y, A13[s].y, bhi.x, bhi.y);
            mma16816(d0, d1, d2, d3, A02[s].x, A13[s].x, A02[s].y, A13[s].y, blo.x, blo.y);
            mma16816(d0, d1, d2, d3, A02[S16 + s].x, A13[S16 + s].x,
                     A02[S16 + s].y, A13[S16 + s].y, bhi.x, bhi.y);
        }
        *(float2*)(outA + ch * 8) = make_float2(d0, d1);
        *(float2*)(outB + ch * 8) = make_float2(d2, d3);
        sA += d0 + d1;  qA += d0 * d0 + d1 * d1;
        sB += d2 + d3;  qB += d2 * d2 + d3 * d3;
    }

    // ---- phase 5: stats reduction (quad -> smem -> global) ----
    #pragma unroll
    for (int off = 1; off <= 2; off <<= 1) {
        sA += __shfl_xor_sync(0xffffffffu, sA, off);
        qA += __shfl_xor_sync(0xffffffffu, qA, off);
        sB += __shfl_xor_sync(0xffffffffu, sB, off);
        qB += __shfl_xor_sync(0xffffffffu, qB, off);
    }
    if (p == 0) {
        atomicAdd(&sred[no + g], sA);
        atomicAdd(&sred[64 + no + g], qA);
        atomicAdd(&sred[no + g + 8], sB);
        atomicAdd(&sred[64 + no + g + 8], qB);
    }
    __syncthreads();
    if (tid < 64)        atomicAdd(&g_sum[statsIdx][tid], sred[tid]);
    else if (tid < 128)  atomicAdd(&g_sqsum[statsIdx][tid - 64], sred[tid]);
}

// ------------------------------ finalize BN ---------------------------------
__global__ void k_finalize(const float* __restrict__ gamma,
                           const float* __restrict__ beta,
                           int idx, float invM) {
    int o = threadIdx.x;
    if (o < O0) {
        float m = g_sum[idx][o] * invM;
        float v = g_sqsum[idx][o] * invM - m * m;
        float a = gamma[o] / sqrtf(v + BN_EPS);
        g_a[idx][o] = a;
        g_c[idx][o] = beta[o] - m * a;
    }
}

// merged finalize for idx 2 (tid<64) and idx 3 (tid>=64)
__global__ void k_finalize23(const float* __restrict__ g2, const float* __restrict__ b2,
                             const float* __restrict__ g3, const float* __restrict__ b3) {
    int t = threadIdx.x;
    int idx = (t < 64) ? 2 : 3;
    int o = t & 63;
    float invM = (t < 64) ? (1.f / (float)M_ALL) : (1.f / (float)M_SC);
    const float* gg = (t < 64) ? g2 : g3;
    const float* bb = (t < 64) ? b2 : b3;
    float m = g_sum[idx][o] * invM;
    float v = g_sqsum[idx][o] * invM - m * m;
    float a = gg[o] / sqrtf(v + BN_EPS);
    g_a[idx][o] = a;
    g_c[idx][o] = bb[o] - m * a;
}

// ------------------------------ final fuse ----------------------------------
__global__ void k_final(float* __restrict__ out) {
    int t = blockIdx.x * blockDim.x + threadIdx.x;
    if (t >= BB * O0 * NN) return;
    int n = t & (NN - 1);
    int o = (t >> 10) & 63;
    int b = t >> 16;
    float a2 = g_a[2][o], c2 = g_c[2][o];
    const float4* S = (const float4*)(g_S0 + (size_t)o * M_ALL + b * (NN * KK) + n * KK);
    float s = 0.f;
    #pragma unroll
    for (int q = 0; q < 4; q++) {
        float4 v = S[q];
        s += fmaxf(fmaf(a2, v.x, c2), 0.f) + fmaxf(fmaf(a2, v.y, c2), 0.f)
           + fmaxf(fmaf(a2, v.z, c2), 0.f) + fmaxf(fmaf(a2, v.w, c2), 0.f);
    }
    float fts = s * (1.f / KK);
    float sc = g_scb[(size_t)o * M_SC + b * NN + n];
    float v = fmaf(g_a[3][o], sc, g_c[3][o]) + fts;
    out[t] = fmaxf(v, 0.f);
}

// ------------------------------- launch -------------------------------------
extern "C" void kernel_launch(void* const* d_in, const int* in_sizes, int n_in,
                              void* d_out, int out_size) {
    const float* points    = (const float*)d_in[0];
    const float* features  = (const float*)d_in[1];
    const int*   edge_list = (const int*)d_in[2];
    const float* edge_feat = (const float*)d_in[3];
    int base = (n_in >= 17 && in_sizes[4] == 1) ? 5 : 4;
    const float* W0   = (const float*)d_in[base + 0];
    const float* W1   = (const float*)d_in[base + 1];
    const float* W2   = (const float*)d_in[base + 2];
    const float* g0   = (const float*)d_in[base + 3];
    const float* b0   = (const float*)d_in[base + 4];
    const float* g1   = (const float*)d_in[base + 5];
    const float* b1   = (const float*)d_in[base + 6];
    const float* g2   = (const float*)d_in[base + 7];
    const float* b2   = (const float*)d_in[base + 8];
    const float* sc_w = (const float*)d_in[base + 9];
    const float* sc_g = (const float*)d_in[base + 10];
    const float* sc_b = (const float*)d_in[base + 11];

    void *pS0, *pS1, *pSC, *pW0, *pW1, *pW2, *pWS;
    cudaGetSymbolAddress(&pS0, g_S0);
    cudaGetSymbolAddress(&pS1, g_S1);
    cudaGetSymbolAddress(&pSC, g_scb);
    cudaGetSymbolAddress(&pW0, g_wx0);
    cudaGetSymbolAddress(&pW1, g_wx1);
    cudaGetSymbolAddress(&pW2, g_wx2);
    cudaGetSymbolAddress(&pWS, g_wxsc);
    float* S0 = (float*)pS0;
    float* S1 = (float*)pS1;
    float* SC = (float*)pSC;

    // smem: 1024 ctrl + Xs (ROWB: layer0 352, layer1/2 288, shortcut 160)
    const int smem0  = 1024 + 128 * 352;   // 46080
    const int smem1  = 1024 + 128 * 288;   // 37888
    const int smemSC = 1024 + 128 * 160;   // 21504
    cudaFuncSetAttribute(k_gemm<68, 0>, cudaFuncAttributeMaxDynamicSharedMemorySize, smem0);
    cudaFuncSetAttribute(k_gemm<64, 1>, cudaFuncAttributeMaxDynamicSharedMemorySize, smem1);
    cudaFuncSetAttribute(k_gemm<32, 2>, cudaFuncAttributeMaxDynamicSharedMemorySize, smemSC);

    k_prep<<<516, 256>>>(W0, W1, W2, sc_w);
    k_scatter<<<(BB * PP + 255) / 256, 256>>>(edge_list, edge_feat);
    k_fb<<<(BB * NN + 255) / 256, 256>>>();
    k_knn<<<64, 128>>>(points);

    k_gemm<32, 2><<<M_SC / 128, 256, smemSC>>>((const uint16_t*)pWS, features, SC, 3, 0, M_SC);
    k_gemm<68, 0><<<M_ALL / 128, 256, smem0>>>((const uint16_t*)pW0, features, S0, 0, 0, M_ALL);
    k_finalize<<<1, 64>>>(g0, b0, 0, 1.f / (float)M_ALL);
    k_gemm<64, 1><<<M_ALL / 128, 256, smem1>>>((const uint16_t*)pW1, S0, S1, 1, 0, M_ALL);
    k_finalize<<<1, 64>>>(g1, b1, 1, 1.f / (float)M_ALL);
    k_gemm<64, 1><<<M_ALL / 128, 256, smem1>>>((const uint16_t*)pW2, S1, S0, 2, 1, M_ALL);
    k_finalize23<<<1, 128>>>(g2, b2, sc_g, sc_b);

    k_final<<<(BB * O0 * NN + 255) / 256, 256>>>((float*)d_out);
}

// round 11
// speedup vs baseline: 1.6964x; 1.0187x over previous
#include <cuda_runtime.h>
#include <cuda_bf16.h>
#include <math.h>
#include <stdint.h>

// ---------------------------------------------------------------------------
// EdgeFeatureConvBlock  (B=32, N=1024, P=8192, K=16, C_IN=32, E_IN=4, OUT=64)
// R11: R10 base (best: 366us) + (1) fb+knn fused into warp-per-node k_knn2
//      (shuffle-only top-16, no block syncs), (2) shortcut GEMM merged into
//      the layer-0 launch (blocks 0-255 shortcut, 256+ layer 0).
//      All GEMM math byte-identical to R10.
// ---------------------------------------------------------------------------

#define BB   32
#define NN   1024
#define PP   8192
#define KK   16
#define CIN  32
#define EIN  4
#define O0   64
#define M_ALL (BB*NN*KK) // 524288
#define M_SC  (BB*NN)    // 32768
#define BN_EPS 1e-5f

// ------------------------- scratch (device globals) ------------------------
__device__ float g_S0[(size_t)O0 * M_ALL];   // [64][M]
__device__ float g_S1[(size_t)O0 * M_ALL];
__device__ float g_scb[(size_t)O0 * M_SC];
__device__ int   g_topidx[M_ALL];
__device__ float g_eft[BB * EIN * NN * KK];
__device__ float g_sum[4][O0];
__device__ float g_sqsum[4][O0];
__device__ float g_a[4][O0];
__device__ float g_c[4][O0];
// W fragment tables: [64][NG][16 u16] permuted (hi groups then lo groups)
__device__ uint16_t g_wx0[64 * 10 * 16];     // layer0: C=68, NG=10
__device__ uint16_t g_wx1[64 * 8 * 16];      // layer1: C=64, NG=8
__device__ uint16_t g_wx2[64 * 8 * 16];      // layer2: C=64, NG=8
__device__ uint16_t g_wxsc[64 * 4 * 16];     // shortcut: C=32, NG=4

// ------------------------------ helpers -------------------------------------
__device__ __forceinline__ void split2(float x, __nv_bfloat16& h, __nv_bfloat16& l) {
    h = __float2bfloat16_rn(x);
    l = __float2bfloat16_rn(x - __bfloat162float(h));
}
__device__ __forceinline__ uint16_t bfbits(__nv_bfloat16 v) {
    return *(uint16_t*)&v;
}
// u16-index inside a 32B k-group for element j (0..15):
// order [0,1,8,9, 2,3,10,11, 4,5,12,13, 6,7,14,15]
__device__ __forceinline__ int pidx(int j) {
    return ((j & 6) << 1) | ((j & 8) >> 2) | (j & 1);
}
__device__ __forceinline__ void st32(char* p, const __nv_bfloat16* v) {
    *(uint4*)p        = ((const uint4*)v)[0];
    *(uint4*)(p + 16) = ((const uint4*)v)[1];
}
__device__ __forceinline__ void mma16816(float& d0, float& d1, float& d2, float& d3,
                                         uint32_t a0, uint32_t a1, uint32_t a2, uint32_t a3,
                                         uint32_t b0, uint32_t b1) {
    asm volatile(
        "mma.sync.aligned.m16n8k16.row.col.f32.bf16.bf16.f32 "
        "{%0,%1,%2,%3}, {%4,%5,%6,%7}, {%8,%9}, {%0,%1,%2,%3};"
        : "+f"(d0), "+f"(d1), "+f"(d2), "+f"(d3)
        : "r"(a0), "r"(a1), "r"(a2), "r"(a3), "r"(b0), "r"(b1));
}

// --------------------- W fragment table build (device fn) -------------------
template<int C>
__device__ __forceinline__ void wext_body(const float* __restrict__ W,
                                          uint16_t* __restrict__ dst) {
    constexpr int SEG = (C + 15) & ~15;
    constexpr int S16 = SEG / 16;
    constexpr int NG  = 2 * S16;
    int tid = threadIdx.x;
    for (int i = tid; i < 64 * NG * 16; i += 256) dst[i] = 0;
    __syncthreads();
    for (int i = tid; i < 64 * C; i += 256) {
        int o = i / C, c = i % C;
        __nv_bfloat16 wh, wl; split2(W[i], wh, wl);
        int g = c >> 4, pj = pidx(c & 15);
        dst[(o * NG + g) * 16 + pj]       = bfbits(wh);
        dst[(o * NG + S16 + g) * 16 + pj] = bfbits(wl);
    }
}

// ------------------- prep: W tables (blocks 0-3) + init (4+) ----------------
__global__ void k_prep(const float* __restrict__ W0, const float* __restrict__ W1,
                       const float* __restrict__ W2, const float* __restrict__ Wsc) {
    int blk = blockIdx.x;
    if (blk == 0)      { wext_body<68>(W0,  g_wx0);  return; }
    else if (blk == 1) { wext_body<64>(W1,  g_wx1);  return; }
    else if (blk == 2) { wext_body<64>(W2,  g_wx2);  return; }
    else if (blk == 3) { wext_body<32>(Wsc, g_wxsc); return; }
    int i = (blk - 4) * blockDim.x + threadIdx.x;
    int stride = (gridDim.x - 4) * blockDim.x;
    for (int j = i; j < M_ALL; j += stride) g_topidx[j] = NN - 1;
    for (int j = i; j < BB * EIN * NN * KK; j += stride) g_eft[j] = 0.f;
    if (i < O0) {
        #pragma unroll
        for (int l = 0; l < 4; l++) { g_sum[l][i] = 0.f; g_sqsum[l][i] = 0.f; }
    }
}

// ------------------------------ edge scatter --------------------------------
__global__ void k_scatter(const int* __restrict__ edge_list,
                          const float* __restrict__ edge_feat) {
    int t = blockIdx.x * blockDim.x + threadIdx.x;
    if (t >= BB * PP) return;
    int b = t / PP, p = t % PP;
    const int* src = edge_list + (size_t)b * 2 * PP;
    const int* dst = src + PP;
    int s = src[p];
    int lo = 0, hi = p;
    while (lo < hi) { int mid = (lo + hi) >> 1; if (src[mid] < s) lo = mid + 1; else hi = mid; }
    int rank = p - lo;
    if (rank < KK) {
        g_topidx[(b * NN + s) * KK + rank] = dst[p];
        #pragma unroll
        for (int e = 0; e < EIN; e++)
            g_eft[((b * EIN + e) * NN + s) * KK + rank] =
                edge_feat[((size_t)b * EIN + e) * PP + p];
    }
}

// --------------- fused fallback-detect + knn (warp per node) ----------------
// Matches reference pd = -xx_n - (-2*dot) - xx_m; self excluded; stable top-16
// (greater value wins; on tie smaller index wins — top_k first occurrence).
__global__ void k_knn2(const float* __restrict__ points) {
    int lane = threadIdx.x & 31;
    int warp = (blockIdx.x * blockDim.x + threadIdx.x) >> 5;
    int nwarps = (gridDim.x * blockDim.x) >> 5;
    for (int bn = warp; bn < BB * NN; bn += nwarps) {
        if (g_topidx[bn * KK] != NN - 1) continue;   // has edges -> skip
        int b = bn >> 10, n = bn & 1023;
        const float* px = points + (size_t)b * 2 * NN;
        const float* py = px + NN;
        float pxn = px[n], pyn = py[n];
        float xxn = pxn * pxn + pyn * pyn;
        float pd[32];
        #pragma unroll
        for (int r = 0; r < 32; r++) {
            int m = r * 32 + lane;
            float xm = px[m], ym = py[m];
            float inner = -2.0f * (pxn * xm + pyn * ym);
            float xxm = xm * xm + ym * ym;
            float v = -xxn - inner - xxm;
            pd[r] = (m == n) ? -INFINITY : v;
        }
        for (int kk = 0; kk < KK; kk++) {
            // local argmax (ascending r = ascending m for this lane; > keeps first)
            float bv = pd[0]; int br = 0;
            #pragma unroll
            for (int r = 1; r < 32; r++)
                if (pd[r] > bv) { bv = pd[r]; br = r; }
            int bi = br * 32 + lane;
            // warp argmax, tie -> smaller index
            #pragma unroll
            for (int off = 16; off; off >>= 1) {
                float ov = __shfl_xor_sync(0xffffffffu, bv, off);
                int   oi = __shfl_xor_sync(0xffffffffu, bi, off);
                if (ov > bv || (ov == bv && oi < bi)) { bv = ov; bi = oi; }
            }
            if (lane == (bi & 31)) pd[bi >> 5] = -INFINITY;
            if (lane == 0) g_topidx[bn * KK + kk] = bi;
        }
    }
}

// --------------------------- mma GEMM + BN stats -----------------------------
// Sout[64][M] = W[64][C] * X[C][M].  X smem = [x_hi | x_lo] (NG = 2*S16
// k-groups). Per k-group s: mma(whi,xhi) + mma(whi,xlo) + mma(wlo,xhi).
// W fragments come from the prebuilt global table (L2-resident).
// CTA: 128 columns (m), 256 threads = 8 warps = 4 channel-groups x 2 m-halves.
// MODE: 0 = gather-build 68ch, 1 = relu(bn(Sin)), 2 = features (shortcut).
template<int C, int MODE>
__device__ __forceinline__ void gemm_body(
    const uint16_t* __restrict__ Wx,
    const float* __restrict__ F,
    float* __restrict__ Sout,
    int statsIdx, int prevIdx, int Mtot, int bid, char* sm)
{
    constexpr int SEG  = (C + 15) & ~15;     // 80 / 64 / 32
    constexpr int S16  = SEG / 16;           // 5 / 4 / 2
    constexpr int NG   = 2 * S16;            // 10 / 8 / 4 k-groups in X
    constexpr int RB0  = NG * 32;
    constexpr int ROWB = RB0 + (((RB0 % 128) == 32 || (RB0 % 128) == 96) ? 0 : 32);
    constexpr int XOFF = 1024;

    float* ca   = (float*)sm;            // [64] bn scale
    float* cb   = ca + 64;               // [64] bn shift
    float* sred = cb + 64;               // [128] block stats (sum | sqsum)
    char*  Xs   = sm + XOFF;

    int tid = threadIdx.x;
    int wid = tid >> 5, lane = tid & 31;
    int gm0 = bid * 128;

    // ---- phase 1: zero / consts ----
    if (tid < 128) sred[tid] = 0.f;
    if (MODE == 1 && tid < 128)
        ((float*)sm)[tid] = (tid < 64) ? g_a[prevIdx][tid] : g_c[prevIdx][tid - 64];
    if (MODE == 0) {   // zero X only when padding exists
        uint4 z = make_uint4(0, 0, 0, 0);
        for (int i = tid * 16; i < 128 * ROWB; i += 256 * 16) *(uint4*)(Xs + i) = z;
    }
    __syncthreads();

    // ---- phase 2: X build ----
    {
        int m = tid >> 1, h = tid & 1;
        int gm = gm0 + m;
        char* rowp = Xs + m * ROWB;
        if (MODE == 0) {
            int b = gm >> 14, mloc = gm & 16383;
            int n = mloc >> 4;
            int ng = g_topidx[gm];
            const float* Fb = F + (size_t)b * CIN * NN;
            #pragma unroll
            for (int blk2 = 0; blk2 < 2; blk2++) {
                __nv_bfloat16 hi[16], lo[16];
                #pragma unroll
                for (int j = 0; j < 16; j++) {
                    int c = blk2 * 16 + j;
                    float xi = Fb[c * NN + n];
                    float v = h ? (Fb[c * NN + ng] - xi) : xi;
                    int pi = pidx(j);
                    split2(v, hi[pi], lo[pi]);
                }
                int gidx = h * 2 + blk2;        // k = h*32 + blk2*16 + j
                st32(rowp + gidx * 32, hi);
                st32(rowp + (S16 + gidx) * 32, lo);
            }
            if (h == 1) {   // edge features k=64..67 -> hi group 4, lo group S16+4
                __nv_bfloat16 eh[4], el[4];
                #pragma unroll
                for (int e = 0; e < 4; e++) {
                    float v = g_eft[(b * EIN + e) * (NN * KK) + mloc];
                    split2(v, eh[e], el[e]);
                }
                uint32_t h01 = (uint32_t)bfbits(eh[0]) | ((uint32_t)bfbits(eh[1]) << 16);
                uint32_t h23 = (uint32_t)bfbits(eh[2]) | ((uint32_t)bfbits(eh[3]) << 16);
                uint32_t l01 = (uint32_t)bfbits(el[0]) | ((uint32_t)bfbits(el[1]) << 16);
                uint32_t l23 = (uint32_t)bfbits(el[2]) | ((uint32_t)bfbits(el[3]) << 16);
                *(uint32_t*)(rowp + 4 * 32)     = h01;
                *(uint32_t*)(rowp + 4 * 32 + 8) = h23;
                *(uint32_t*)(rowp + (S16 + 4) * 32)     = l01;
                *(uint32_t*)(rowp + (S16 + 4) * 32 + 8) = l23;
            }
        } else if (MODE == 1) {
            #pragma unroll
            for (int blk2 = 0; blk2 < 2; blk2++) {
                __nv_bfloat16 hi[16], lo[16];
                #pragma unroll
                for (int j = 0; j < 16; j++) {
                    int c = h * 32 + blk2 * 16 + j;
                    float v = F[(size_t)c * Mtot + gm];
                    float x = fmaxf(fmaf(ca[c], v, cb[c]), 0.f);
                    int pi = pidx(j);
                    split2(x, hi[pi], lo[pi]);
                }
                int gidx = h * 2 + blk2;
                st32(rowp + gidx * 32, hi);
                st32(rowp + (S16 + gidx) * 32, lo);
            }
        } else {            // MODE 2 (shortcut, C=32)
            int b = gm >> 10, n = gm & 1023;
            __nv_bfloat16 hi[16], lo[16];
            #pragma unroll
            for (int j = 0; j < 16; j++) {
                int c = h * 16 + j;
                float v = F[(size_t)(b * CIN + c) * NN + n];
                int pi = pidx(j);
                split2(v, hi[pi], lo[pi]);
            }
            st32(rowp + h * 32, hi);
            st32(rowp + (S16 + h) * 32, lo);
        }
    }

    // ---- phase 3: hoist W fragments from global table (cached) ----
    int cg = wid & 3, mh = wid >> 2;
    int no = cg * 16;
    int g = lane >> 2, p = lane & 3;
    uint2 A02[NG], A13[NG];
    #pragma unroll
    for (int s = 0; s < NG; s++) {
        A02[s] = *(const uint2*)(Wx + (no + g) * (NG * 16) + s * 16 + p * 4);
        A13[s] = *(const uint2*)(Wx + (no + g + 8) * (NG * 16) + s * 16 + p * 4);
    }
    __syncthreads();

    // ---- phase 4: mma main loop ----
    float sA = 0.f, qA = 0.f, sB = 0.f, qB = 0.f;
    float* outA = Sout + (size_t)(no + g) * Mtot + gm0 + mh * 64 + 2 * p;
    float* outB = Sout + (size_t)(no + g + 8) * Mtot + gm0 + mh * 64 + 2 * p;
    #pragma unroll
    for (int ch = 0; ch < 8; ch++) {
        int m0 = mh * 64 + ch * 8;
        const char* brow = Xs + (m0 + g) * ROWB + p * 8;
        float d0 = 0.f, d1 = 0.f, d2 = 0.f, d3 = 0.f;
        #pragma unroll
        for (int s = 0; s < S16; s++) {
            uint2 bhi = *(const uint2*)(brow + s * 32);
            uint2 blo = *(const uint2*)(brow + (S16 + s) * 32);
            mma16816(d0, d1, d2, d3, A02[s].x, A13[s].x, A02[s].y, A13[s].y, bhi.x, bhi.y);
            mma16816(d0, d1, d2, d3, A02[s].x, A13[s].x, A02[s].y, A13[s].y, blo.x, blo.y);
            mma16816(d0, d1, d2, d3, A02[S16 + s].x, A13[S16 + s].x,
                     A02[S16 + s].y, A13[S16 + s].y, bhi.x, bhi.y);
        }
        *(float2*)(outA + ch * 8) = make_float2(d0, d1);
        *(float2*)(outB + ch * 8) = make_float2(d2, d3);
        sA += d0 + d1;  qA += d0 * d0 + d1 * d1;
        sB += d2 + d3;  qB += d2 * d2 + d3 * d3;
    }

    // ---- phase 5: stats reduction (quad -> smem -> global) ----
    #pragma unroll
    for (int off = 1; off <= 2; off <<= 1) {
        sA += __shfl_xor_sync(0xffffffffu, sA, off);
        qA += __shfl_xor_sync(0xffffffffu, qA, off);
        sB += __shfl_xor_sync(0xffffffffu, sB, off);
        qB += __shfl_xor_sync(0xffffffffu, qB, off);
    }
    if (p == 0) {
        atomicAdd(&sred[no + g], sA);
        atomicAdd(&sred[64 + no + g], qA);
        atomicAdd(&sred[no + g + 8], sB);
        atomicAdd(&sred[64 + no + g + 8], qB);
    }
    __syncthreads();
    if (tid < 64)        atomicAdd(&g_sum[statsIdx][tid], sred[tid]);
    else if (tid < 128)  atomicAdd(&g_sqsum[statsIdx][tid - 64], sred[tid]);
}

// layer0 + shortcut in one launch: blocks 0-255 shortcut, 256+ layer 0
__global__ __launch_bounds__(256, 3) void k_gemm0sc(
    const uint16_t* __restrict__ Wx0, const uint16_t* __restrict__ WxSC,
    const float* __restrict__ F, float* __restrict__ S0, float* __restrict__ SC)
{
    extern __shared__ __align__(16) char sm[];
    if (blockIdx.x < M_SC / 128)
        gemm_body<32, 2>(WxSC, F, SC, 3, 0, M_SC, blockIdx.x, sm);
    else
        gemm_body<68, 0>(Wx0, F, S0, 0, 0, M_ALL, blockIdx.x - M_SC / 128, sm);
}

template<int C, int MODE>
__global__ __launch_bounds__(256, 3) void k_gemm(
    const uint16_t* __restrict__ Wx,
    const float* __restrict__ F,
    float* __restrict__ Sout,
    int statsIdx, int prevIdx, int Mtot)
{
    extern __shared__ __align__(16) char sm[];
    gemm_body<C, MODE>(Wx, F, Sout, statsIdx, prevIdx, Mtot, blockIdx.x, sm);
}

// ------------------------------ finalize BN ---------------------------------
__global__ void k_finalize(const float* __restrict__ gamma,
                           const float* __restrict__ beta,
                           int idx, float invM) {
    int o = threadIdx.x;
    if (o < O0) {
        float m = g_sum[idx][o] * invM;
        float v = g_sqsum[idx][o] * invM - m * m;
        float a = gamma[o] / sqrtf(v + BN_EPS);
        g_a[idx][o] = a;
        g_c[idx][o] = beta[o] - m * a;
    }
}

// merged finalize for idx 2 (tid<64) and idx 3 (tid>=64)
__global__ void k_finalize23(const float* __restrict__ g2, const float* __restrict__ b2,
                             const float* __restrict__ g3, const float* __restrict__ b3) {
    int t = threadIdx.x;
    int idx = (t < 64) ? 2 : 3;
    int o = t & 63;
    float invM = (t < 64) ? (1.f / (float)M_ALL) : (1.f / (float)M_SC);
    const float* gg = (t < 64) ? g2 : g3;
    const float* bb = (t < 64) ? b2 : b3;
    float m = g_sum[idx][o] * invM;
    float v = g_sqsum[idx][o] * invM - m * m;
    float a = gg[o] / sqrtf(v + BN_EPS);
    g_a[idx][o] = a;
    g_c[idx][o] = bb[o] - m * a;
}

// ------------------------------ final fuse ----------------------------------
__global__ void k_final(float* __restrict__ out) {
    int t = blockIdx.x * blockDim.x + threadIdx.x;
    if (t >= BB * O0 * NN) return;
    int n = t & (NN - 1);
    int o = (t >> 10) & 63;
    int b = t >> 16;
    float a2 = g_a[2][o], c2 = g_c[2][o];
    const float4* S = (const float4*)(g_S0 + (size_t)o * M_ALL + b * (NN * KK) + n * KK);
    float s = 0.f;
    #pragma unroll
    for (int q = 0; q < 4; q++) {
        float4 v = S[q];
        s += fmaxf(fmaf(a2, v.x, c2), 0.f) + fmaxf(fmaf(a2, v.y, c2), 0.f)
           + fmaxf(fmaf(a2, v.z, c2), 0.f) + fmaxf(fmaf(a2, v.w, c2), 0.f);
    }
    float fts = s * (1.f / KK);
    float sc = g_scb[(size_t)o * M_SC + b * NN + n];
    float v = fmaf(g_a[3][o], sc, g_c[3][o]) + fts;
    out[t] = fmaxf(v, 0.f);
}

// ------------------------------- launch -------------------------------------
extern "C" void kernel_launch(void* const* d_in, const int* in_sizes, int n_in,
                              void* d_out, int out_size) {
    const float* points    = (const float*)d_in[0];
    const float* features  = (const float*)d_in[1];
    const int*   edge_list = (const int*)d_in[2];
    const float* edge_feat = (const float*)d_in[3];
    int base = (n_in >= 17 && in_sizes[4] == 1) ? 5 : 4;
    const float* W0   = (const float*)d_in[base + 0];
    const float* W1   = (const float*)d_in[base + 1];
    const float* W2   = (const float*)d_in[base + 2];
    const float* g0   = (const float*)d_in[base + 3];
    const float* b0   = (const float*)d_in[base + 4];
    const float* g1   = (const float*)d_in[base + 5];
    const float* b1   = (const float*)d_in[base + 6];
    const float* g2   = (const float*)d_in[base + 7];
    const float* b2   = (const float*)d_in[base + 8];
    const float* sc_w = (const float*)d_in[base + 9];
    const float* sc_g = (const float*)d_in[base + 10];
    const float* sc_b = (const float*)d_in[base + 11];

    void *pS0, *pS1, *pSC, *pW0, *pW1, *pW2, *pWS;
    cudaGetSymbolAddress(&pS0, g_S0);
    cudaGetSymbolAddress(&pS1, g_S1);
    cudaGetSymbolAddress(&pSC, g_scb);
    cudaGetSymbolAddress(&pW0, g_wx0);
    cudaGetSymbolAddress(&pW1, g_wx1);
    cudaGetSymbolAddress(&pW2, g_wx2);
    cudaGetSymbolAddress(&pWS, g_wxsc);
    float* S0 = (float*)pS0;
    float* S1 = (float*)pS1;
    float* SC = (float*)pSC;

    // smem: 1024 ctrl + Xs (ROWB: layer0 352, layer1/2 288, shortcut 160)
    const int smem0  = 1024 + 128 * 352;   // 46080 (covers shortcut's 21504 too)
    const int smem1  = 1024 + 128 * 288;   // 37888
    cudaFuncSetAttribute(k_gemm0sc, cudaFuncAttributeMaxDynamicSharedMemorySize, smem0);
    cudaFuncSetAttribute(k_gemm<64, 1>, cudaFuncAttributeMaxDynamicSharedMemorySize, smem1);

    k_prep<<<516, 256>>>(W0, W1, W2, sc_w);
    k_scatter<<<(BB * PP + 255) / 256, 256>>>(edge_list, edge_feat);
    k_knn2<<<256, 256>>>(points);

    k_gemm0sc<<<M_SC / 128 + M_ALL / 128, 256, smem0>>>(
        (const uint16_t*)pW0, (const uint16_t*)pWS, features, S0, SC);
    k_finalize<<<1, 64>>>(g0, b0, 0, 1.f / (float)M_ALL);
    k_gemm<64, 1><<<M_ALL / 128, 256, smem1>>>((const uint16_t*)pW1, S0, S1, 1, 0, M_ALL);
    k_finalize<<<1, 64>>>(g1, b1, 1, 1.f / (float)M_ALL);
    k_gemm<64, 1><<<M_ALL / 128, 256, smem1>>>((const uint16_t*)pW2, S1, S0, 2, 1, M_ALL);
    k_finalize23<<<1, 128>>>(g2, b2, sc_g, sc_b);

    k_final<<<(BB * O0 * NN + 255) / 256, 256>>>((float*)d_out);
}